// round 2
// baseline (speedup 1.0000x reference)
#include <cuda_runtime.h>
#include <math.h>

#define BATCH 16
#define CHAN  256
#define TLEN  4096
#define NLAYERS 8
#define KEFF  512           // 2 taps * 256 cin, stacked K dimension

// Ping-pong activation scratch + transposed weights (allowed: __device__ globals)
__device__ float g_bufA[(size_t)BATCH * CHAN * TLEN];
__device__ float g_bufB[(size_t)BATCH * CHAN * TLEN];
// [layer][fg][k][cout], k<256 -> tap1 (current), k>=256 -> tap0 (shifted by d)
__device__ float g_wT[(size_t)NLAYERS * 2 * KEFF * CHAN];

// ---------------------------------------------------------------------------
// Weight transpose: w[l][cout][cin][tap] -> g_wT[l][fg][k][cout]
// ---------------------------------------------------------------------------
__global__ void transpose_weights_kernel(const float* __restrict__ fw,
                                         const float* __restrict__ gw) {
    int idx = blockIdx.x * blockDim.x + threadIdx.x;
    const int total = NLAYERS * 2 * KEFF * CHAN;
    if (idx >= total) return;
    int cout = idx & (CHAN - 1);
    int k    = (idx >> 8) & (KEFF - 1);
    int fg   = (idx >> 17) & 1;
    int l    = idx >> 18;
    const float* w = fg ? gw : fw;
    int cin = k & (CHAN - 1);
    int tap = (k < CHAN) ? 1 : 0;  // first half of K = current sample (tap 1)
    g_wT[idx] = w[(((size_t)l * CHAN + cout) * CHAN + cin) * 2 + tap];
}

// ---------------------------------------------------------------------------
// Fused layer: F = tanh(conv_f(Z)), G = sigmoid(conv_g(Z)), Zs = F*G,
// Zout (+)= Zs. Block tile: 64 couts x 128 t, one batch. 256 threads,
// each thread: 4x8 outputs for BOTH F and G (64 fp32 accumulators).
// K loop: 32 chunks of 16 over stacked K=512; chunks >=16 use the
// d-shifted X tile (tap 0), causal zero-fill for t-d < 0.
// ---------------------------------------------------------------------------
__global__ __launch_bounds__(256, 2)
void wavenet_layer_kernel(const float* __restrict__ Zin,
                          const float* __restrict__ wTf,
                          const float* __restrict__ wTg,
                          const float* __restrict__ fb,
                          const float* __restrict__ gb,
                          float* __restrict__ Zsout,
                          float* __restrict__ Zout,
                          int dil, int first)
{
    __shared__ float sWf[16][64];
    __shared__ float sWg[16][64];
    __shared__ float sX[16][128];

    const int tid = threadIdx.x;
    const int t0  = blockIdx.x * 128;
    const int m0  = blockIdx.y * 64;
    const int b   = blockIdx.z;

    const int r  = tid >> 4;       // 0..15 : cout group
    const int c  = tid & 15;       // 0..15 : t group
    const int mr = r * 4;
    const int tc = c * 8;

    float accF[4][8], accG[4][8];
#pragma unroll
    for (int i = 0; i < 4; ++i)
#pragma unroll
        for (int j = 0; j < 8; ++j) { accF[i][j] = 0.f; accG[i][j] = 0.f; }

    const size_t baseB = (size_t)b * CHAN * TLEN;

    for (int kb = 0; kb < 32; ++kb) {
        const int k0    = kb * 16;
        const int cin0  = (kb & 15) * 16;
        const int shift = (kb >= 16) ? dil : 0;

        __syncthreads();
        // weights: 16x64 each, coalesced from transposed layout
#pragma unroll
        for (int u = 0; u < 4; ++u) {
            int idx = tid + u * 256;
            int kk = idx >> 6, m = idx & 63;
            sWf[kk][m] = wTf[(size_t)(k0 + kk) * CHAN + m0 + m];
            sWg[kk][m] = wTg[(size_t)(k0 + kk) * CHAN + m0 + m];
        }
        // X tile: 16 cin rows x 128 t, coalesced, causal zero-fill
#pragma unroll
        for (int u = 0; u < 8; ++u) {
            int idx = tid + u * 256;
            int kk = idx >> 7, tt = idx & 127;
            int tsrc = t0 + tt - shift;
            sX[kk][tt] = (tsrc >= 0)
                ? __ldg(&Zin[baseB + (size_t)(cin0 + kk) * TLEN + tsrc])
                : 0.f;
        }
        __syncthreads();

#pragma unroll
        for (int kk = 0; kk < 16; ++kk) {
            float xr[8];
#pragma unroll
            for (int j = 0; j < 8; ++j) xr[j] = sX[kk][tc + j];
            float wf[4], wg[4];
#pragma unroll
            for (int i = 0; i < 4; ++i) { wf[i] = sWf[kk][mr + i]; wg[i] = sWg[kk][mr + i]; }
#pragma unroll
            for (int i = 0; i < 4; ++i)
#pragma unroll
                for (int j = 0; j < 8; ++j) {
                    accF[i][j] = fmaf(wf[i], xr[j], accF[i][j]);
                    accG[i][j] = fmaf(wg[i], xr[j], accG[i][j]);
                }
        }
    }

    // Epilogue: bias + tanh * sigmoid, vectorized stores
#pragma unroll
    for (int i = 0; i < 4; ++i) {
        const int cout = m0 + mr + i;
        const float fbv = __ldg(&fb[cout]);
        const float gbv = __ldg(&gb[cout]);
        float z[8];
#pragma unroll
        for (int j = 0; j < 8; ++j) {
            float F = accF[i][j] + fbv;
            float G = accG[i][j] + gbv;
            // sigmoid(x) = 0.5*(1 + tanh(x/2))  (exact identity)
            z[j] = tanhf(F) * (0.5f * tanhf(0.5f * G) + 0.5f);
        }
        const size_t o = baseB + (size_t)cout * TLEN + t0 + tc;
        float4 z0 = make_float4(z[0], z[1], z[2], z[3]);
        float4 z1 = make_float4(z[4], z[5], z[6], z[7]);
        float4* zs = reinterpret_cast<float4*>(Zsout + o);
        float4* ao = reinterpret_cast<float4*>(Zout + o);
        zs[0] = z0; zs[1] = z1;
        if (first) {
            ao[0] = z0; ao[1] = z1;
        } else {
            float4 a0 = ao[0], a1 = ao[1];
            a0.x += z0.x; a0.y += z0.y; a0.z += z0.z; a0.w += z0.w;
            a1.x += z1.x; a1.y += z1.y; a1.z += z1.z; a1.w += z1.w;
            ao[0] = a0; ao[1] = a1;
        }
    }
}

// ---------------------------------------------------------------------------
// Launch: transpose weights once, then 8 dependent layer kernels.
// All on the capture stream (default), no sync, no allocation.
// ---------------------------------------------------------------------------
extern "C" void kernel_launch(void* const* d_in, const int* in_sizes, int n_in,
                              void* d_out, int out_size) {
    const float* ys = (const float*)d_in[0];
    const float* fw = (const float*)d_in[1];
    const float* fb = (const float*)d_in[2];
    const float* gw = (const float*)d_in[3];
    const float* gb = (const float*)d_in[4];
    float* out = (float*)d_out;

    float *bufA, *bufB, *wT;
    cudaGetSymbolAddress((void**)&bufA, g_bufA);
    cudaGetSymbolAddress((void**)&bufB, g_bufB);
    cudaGetSymbolAddress((void**)&wT,   g_wT);

    {
        const int total = NLAYERS * 2 * KEFF * CHAN;
        transpose_weights_kernel<<<(total + 255) / 256, 256>>>(fw, gw);
    }

    dim3 grid(TLEN / 128, CHAN / 64, BATCH);
    dim3 block(256);

    float* bufs[2] = { bufA, bufB };
    const float* zin = ys;
    for (int l = 0; l < NLAYERS; ++l) {
        const int dil = 1 << l;
        const float* wtf = wT + ((size_t)l * 2 + 0) * KEFF * CHAN;
        const float* wtg = wT + ((size_t)l * 2 + 1) * KEFF * CHAN;
        float* zo = bufs[l & 1];
        wavenet_layer_kernel<<<grid, block>>>(zin, wtf, wtg,
                                              fb + l * CHAN, gb + l * CHAN,
                                              zo, out, dil, (l == 0) ? 1 : 0);
        zin = zo;
    }
}

// round 4
// speedup vs baseline: 2.4045x; 2.4045x over previous
#include <cuda_runtime.h>
#include <cuda_bf16.h>
#include <cstdint>
#include <math.h>

#define BATCH 16
#define CHAN  256
#define TLEN  4096
#define NLAYERS 8
#define KEFF  512            // 2 taps * 256 cin stacked
#define NCHUNK 16            // 16 chunks of k=32

// ---------------- device scratch -------------------------------------------
// Activations, [b][t][c] layout, bf16 hi/lo split, ping-pong
__device__ __nv_bfloat16 g_xhiA[(size_t)BATCH * TLEN * CHAN];
__device__ __nv_bfloat16 g_xloA[(size_t)BATCH * TLEN * CHAN];
__device__ __nv_bfloat16 g_xhiB[(size_t)BATCH * TLEN * CHAN];
__device__ __nv_bfloat16 g_xloB[(size_t)BATCH * TLEN * CHAN];
// Weights: [l][fg][hilo][cout][k]  k-major bf16; k<256 -> tap1(current), k>=256 -> tap0
__device__ __nv_bfloat16 g_wbf[(size_t)NLAYERS * 2 * 2 * CHAN * KEFF];

// ---------------- smem geometry --------------------------------------------
// Per stage: A(hi) 128 rows x 80B = 10240, A(lo) 10240,
//            W 4 arrays (fg x hilo) x 64 rows x 80B = 20480. Stage = 40960.
#define AROW   80
#define STAGE_BYTES 40960
#define SM_TOTAL (2 * STAGE_BYTES)   // 81920; epilogue z tile (64x132 f32 = 33792) reuses stage 0

// ---------------- asm helpers ----------------------------------------------
__device__ __forceinline__ uint32_t smem_u32(const void* p) {
    uint32_t a;
    asm("{ .reg .u64 t; cvta.to.shared.u64 t, %1; cvt.u32.u64 %0, t; }" : "=r"(a) : "l"(p));
    return a;
}
__device__ __forceinline__ void cp16(uint32_t dst, const void* src, uint32_t srcsize) {
    asm volatile("cp.async.cg.shared.global [%0], [%1], 16, %2;"
                 :: "r"(dst), "l"(src), "r"(srcsize) : "memory");
}
#define CP_COMMIT() asm volatile("cp.async.commit_group;" ::: "memory")
#define CP_WAIT(n)  asm volatile("cp.async.wait_group %0;" :: "n"(n) : "memory")

__device__ __forceinline__ void ldsm4(uint32_t* r, uint32_t addr) {
    asm volatile("ldmatrix.sync.aligned.m8n8.x4.shared.b16 {%0,%1,%2,%3}, [%4];"
                 : "=r"(r[0]), "=r"(r[1]), "=r"(r[2]), "=r"(r[3]) : "r"(addr));
}
__device__ __forceinline__ void mma16816(float* d, const uint32_t* a, const uint32_t* b) {
    asm volatile("mma.sync.aligned.m16n8k16.row.col.f32.bf16.bf16.f32 "
                 "{%0,%1,%2,%3}, {%4,%5,%6,%7}, {%8,%9}, {%0,%1,%2,%3};"
                 : "+f"(d[0]), "+f"(d[1]), "+f"(d[2]), "+f"(d[3])
                 : "r"(a[0]), "r"(a[1]), "r"(a[2]), "r"(a[3]), "r"(b[0]), "r"(b[1]));
}

// ---------------- prep kernels ---------------------------------------------
__global__ void prep_weights(const float* __restrict__ fw, const float* __restrict__ gw) {
    int idx = blockIdx.x * blockDim.x + threadIdx.x;   // [l][fg][cout][k]
    const int total = NLAYERS * 2 * CHAN * KEFF;
    if (idx >= total) return;
    int k    = idx & (KEFF - 1);
    int cout = (idx >> 9) & (CHAN - 1);
    int fg   = (idx >> 17) & 1;
    int l    = idx >> 18;
    const float* w = fg ? gw : fw;
    int cin = k & (CHAN - 1);
    int tap = (k < CHAN) ? 1 : 0;
    float v = w[(((size_t)l * CHAN + cout) * CHAN + cin) * 2 + tap];
    __nv_bfloat16 hi = __float2bfloat16_rn(v);
    __nv_bfloat16 lo = __float2bfloat16_rn(v - __bfloat162float(hi));
    size_t base = (((size_t)l * 2 + fg) * 2) * (CHAN * KEFF) + (size_t)cout * KEFF + k;
    g_wbf[base] = hi;
    g_wbf[base + (size_t)CHAN * KEFF] = lo;
}

// [b][c][t] f32 -> [b][t][c] bf16 hi/lo, tiled transpose
__global__ void prep_input(const float* __restrict__ ys) {
    __shared__ float tile[32][33];
    const int b  = blockIdx.z;
    const int c0 = blockIdx.y * 32;
    const int t0 = blockIdx.x * 32;
    const int tx = threadIdx.x, ty = threadIdx.y;   // 32 x 8
#pragma unroll
    for (int i = 0; i < 32; i += 8)
        tile[ty + i][tx] = ys[((size_t)b * CHAN + c0 + ty + i) * TLEN + t0 + tx];
    __syncthreads();
#pragma unroll
    for (int i = 0; i < 32; i += 8) {
        float v = tile[tx][ty + i];
        __nv_bfloat16 hi = __float2bfloat16_rn(v);
        __nv_bfloat16 lo = __float2bfloat16_rn(v - __bfloat162float(hi));
        size_t o = (size_t)b * TLEN * CHAN + (size_t)(t0 + ty + i) * CHAN + c0 + tx;
        g_xhiA[o] = hi;
        g_xloA[o] = lo;
    }
}

// ---------------- per-chunk loader (all cp.async) ---------------------------
__device__ __forceinline__ void load_chunk(
    int c, uint32_t sstage,
    const __nv_bfloat16* __restrict__ Xhi, const __nv_bfloat16* __restrict__ Xlo,
    const __nv_bfloat16* __restrict__ Wl,
    int tid, int t0, int cout0, int dil)
{
    const int shift = (c >= 8) ? dil : 0;
    const int cin0  = (c & 7) * 32;
    // A: 128 rows x 64B x 2(hilo) = 1024 quads
#pragma unroll
    for (int j = 0; j < 4; ++j) {
        int id = tid + j * 256;
        int quad = id & 3, tt = (id >> 2) & 127, hilo = id >> 9;
        int ts = t0 + tt - shift;
        const __nv_bfloat16* xb = hilo ? Xlo : Xhi;
        int tsc = ts >= 0 ? ts : 0;
        const __nv_bfloat16* src = xb + (size_t)tsc * CHAN + cin0 + quad * 8;
        uint32_t dst = sstage + hilo * 10240 + tt * AROW + quad * 16;
        cp16(dst, src, ts >= 0 ? 16u : 0u);
    }
    // W: 4 arrays x 64 rows x 64B = 1024 quads
#pragma unroll
    for (int j = 0; j < 4; ++j) {
        int id = tid + j * 256;
        int quad = id & 3, row = (id >> 2) & 63, arr = id >> 8;
        const __nv_bfloat16* src = Wl + (size_t)arr * (CHAN * KEFF)
                                 + (size_t)(cout0 + row) * KEFF + c * 32 + quad * 8;
        uint32_t dst = sstage + 20480 + arr * 5120 + row * AROW + quad * 16;
        cp16(dst, src, 16u);
    }
}

// ---------------- fused HMMA layer kernel -----------------------------------
__global__ __launch_bounds__(256, 2)
void wavenet_mma_layer(const __nv_bfloat16* __restrict__ Xhi,
                       const __nv_bfloat16* __restrict__ Xlo,
                       const __nv_bfloat16* __restrict__ Wl,
                       const float* __restrict__ fb,
                       const float* __restrict__ gb,
                       __nv_bfloat16* __restrict__ Yhi,
                       __nv_bfloat16* __restrict__ Ylo,
                       float* __restrict__ Zout,
                       int dil, int first)
{
    extern __shared__ char smem[];
    const uint32_t sb = smem_u32(smem);
    const int tid  = threadIdx.x;
    const int wid  = tid >> 5;
    const int lane = tid & 31;
    const int t0    = blockIdx.x * 128;
    const int cout0 = blockIdx.y * 64;
    const int b     = blockIdx.z;

    const __nv_bfloat16* Xh = Xhi + (size_t)b * TLEN * CHAN;
    const __nv_bfloat16* Xl = Xlo + (size_t)b * TLEN * CHAN;

    const int m0 = (wid & 3) * 32;   // t within tile
    const int n0 = (wid >> 2) * 32;  // cout within tile

    float accF[2][4][4], accG[2][4][4];
#pragma unroll
    for (int mi = 0; mi < 2; ++mi)
#pragma unroll
        for (int nt = 0; nt < 4; ++nt)
#pragma unroll
            for (int e = 0; e < 4; ++e) { accF[mi][nt][e] = 0.f; accG[mi][nt][e] = 0.f; }

    // prologue: chunk 0 -> stage 0
    load_chunk(0, sb, Xh, Xl, Wl, tid, t0, cout0, dil);
    CP_COMMIT();

    // lane-derived ldmatrix row/col offsets
    const uint32_t a_row = (uint32_t)(lane & 15);
    const uint32_t a_kb  = (uint32_t)((lane >> 4) * 16);
    const uint32_t b_row = (uint32_t)(((lane >> 4) * 8) + (lane & 7));
    const uint32_t b_kb  = (uint32_t)(((lane >> 3) & 1) * 16);

#define MMA_FG(ACC)                                                             \
    do {                                                                        \
        _Pragma("unroll")                                                       \
        for (int mi = 0; mi < 2; ++mi)                                          \
            _Pragma("unroll")                                                   \
            for (int nt2 = 0; nt2 < 2; ++nt2)                                   \
                _Pragma("unroll")                                               \
                for (int s = 0; s < 2; ++s) {                                   \
                    float* d = ACC[mi][nt2 * 2 + s];                            \
                    mma16816(d, a_hi[mi], &b_hi[nt2][s * 2]);                   \
                    mma16816(d, a_hi[mi], &b_lo[nt2][s * 2]);                   \
                    mma16816(d, a_lo[mi], &b_hi[nt2][s * 2]);                   \
                }                                                               \
    } while (0)

    for (int c = 0; c < NCHUNK; ++c) {
        const uint32_t scur = sb + (uint32_t)(c & 1) * STAGE_BYTES;
        if (c + 1 < NCHUNK) {
            load_chunk(c + 1, sb + (uint32_t)((c + 1) & 1) * STAGE_BYTES,
                       Xh, Xl, Wl, tid, t0, cout0, dil);
            CP_COMMIT();
            CP_WAIT(1);
        } else {
            CP_WAIT(0);
        }
        __syncthreads();

        const uint32_t sA = scur;
        const uint32_t sW = scur + 20480;
#pragma unroll
        for (int ks = 0; ks < 2; ++ks) {
            uint32_t a_hi[2][4], a_lo[2][4];
#pragma unroll
            for (int mi = 0; mi < 2; ++mi) {
                uint32_t adr = sA + (m0 + mi * 16 + a_row) * AROW + ks * 32 + a_kb;
                ldsm4(a_hi[mi], adr);
                ldsm4(a_lo[mi], adr + 10240);
            }
            {   // fg = 0 (filter)
                uint32_t b_hi[2][4], b_lo[2][4];
#pragma unroll
                for (int nt2 = 0; nt2 < 2; ++nt2) {
                    uint32_t off = (n0 + nt2 * 16 + b_row) * AROW + ks * 32 + b_kb;
                    ldsm4(b_hi[nt2], sW + 0 * 5120 + off);
                    ldsm4(b_lo[nt2], sW + 1 * 5120 + off);
                }
                MMA_FG(accF);
            }
            {   // fg = 1 (gate)
                uint32_t b_hi[2][4], b_lo[2][4];
#pragma unroll
                for (int nt2 = 0; nt2 < 2; ++nt2) {
                    uint32_t off = (n0 + nt2 * 16 + b_row) * AROW + ks * 32 + b_kb;
                    ldsm4(b_hi[nt2], sW + 2 * 5120 + off);
                    ldsm4(b_lo[nt2], sW + 3 * 5120 + off);
                }
                MMA_FG(accG);
            }
        }
        __syncthreads();
    }
#undef MMA_FG

    // ---- epilogue: activation in regs -> z smem tile -> coalesced writeout --
    float* zs = reinterpret_cast<float*>(smem);   // 64 x 132 f32
    {
        const int g  = lane >> 2;
        const int tg = lane & 3;
        float fbv[4][2], gbv[4][2];
#pragma unroll
        for (int nt = 0; nt < 4; ++nt)
#pragma unroll
            for (int p = 0; p < 2; ++p) {
                int cout = cout0 + n0 + nt * 8 + 2 * tg + p;
                fbv[nt][p] = __ldg(fb + cout);
                gbv[nt][p] = __ldg(gb + cout);
            }
#pragma unroll
        for (int mi = 0; mi < 2; ++mi)
#pragma unroll
            for (int nt = 0; nt < 4; ++nt)
#pragma unroll
                for (int e = 0; e < 4; ++e) {
                    int t_loc = m0 + mi * 16 + g + (e >> 1) * 8;
                    int c_loc = n0 + nt * 8 + 2 * tg + (e & 1);
                    float F = accF[mi][nt][e] + fbv[nt][e & 1];
                    float G = accG[mi][nt][e] + gbv[nt][e & 1];
                    float z = tanhf(F) * (0.5f * tanhf(0.5f * G) + 0.5f);
                    zs[c_loc * 132 + t_loc] = z;
                }
    }
    __syncthreads();

    const size_t yb = (size_t)b * TLEN * CHAN;
    const size_t zb = (size_t)b * CHAN * TLEN;
    // Y: [b][t][c] bf16 hi/lo, lanes walk c
#pragma unroll
    for (int i = 0; i < 32; ++i) {
        int id = tid + i * 256;
        int cl = id & 63, t = id >> 6;
        float z = zs[cl * 132 + t];
        __nv_bfloat16 h = __float2bfloat16_rn(z);
        __nv_bfloat16 l = __float2bfloat16_rn(z - __bfloat162float(h));
        size_t o = yb + (size_t)(t0 + t) * CHAN + cout0 + cl;
        Yhi[o] = h;
        Ylo[o] = l;
    }
    // Zout: [b][c][t] f32, lanes walk t
#pragma unroll
    for (int i = 0; i < 32; ++i) {
        int id = tid + i * 256;
        int t = id & 127, cl = id >> 7;
        float z = zs[cl * 132 + t];
        size_t o = zb + (size_t)(cout0 + cl) * TLEN + t0 + t;
        if (first) Zout[o] = z;
        else       Zout[o] += z;
    }
}

// ---------------- launch ----------------------------------------------------
extern "C" void kernel_launch(void* const* d_in, const int* in_sizes, int n_in,
                              void* d_out, int out_size) {
    const float* ys = (const float*)d_in[0];
    const float* fw = (const float*)d_in[1];
    const float* fb = (const float*)d_in[2];
    const float* gw = (const float*)d_in[3];
    const float* gb = (const float*)d_in[4];
    float* out = (float*)d_out;

    __nv_bfloat16 *xhiA, *xloA, *xhiB, *xloB, *wbf;
    cudaGetSymbolAddress((void**)&xhiA, g_xhiA);
    cudaGetSymbolAddress((void**)&xloA, g_xloA);
    cudaGetSymbolAddress((void**)&xhiB, g_xhiB);
    cudaGetSymbolAddress((void**)&xloB, g_xloB);
    cudaGetSymbolAddress((void**)&wbf,  g_wbf);

    static int attr_done = 0;
    if (!attr_done) {
        cudaFuncSetAttribute(wavenet_mma_layer,
                             cudaFuncAttributeMaxDynamicSharedMemorySize, SM_TOTAL);
        attr_done = 1;
    }

    {
        const int total = NLAYERS * 2 * CHAN * KEFF;
        prep_weights<<<(total + 255) / 256, 256>>>(fw, gw);
        dim3 tg(TLEN / 32, CHAN / 32, BATCH);
        prep_input<<<tg, dim3(32, 8)>>>(ys);
    }

    dim3 grid(TLEN / 128, CHAN / 64, BATCH);
    const __nv_bfloat16* xhi = xhiA;
    const __nv_bfloat16* xlo = xloA;
    __nv_bfloat16* yhis[2] = { xhiB, xhiA };
    __nv_bfloat16* ylos[2] = { xloB, xloA };
    for (int l = 0; l < NLAYERS; ++l) {
        __nv_bfloat16* yhi = yhis[l & 1];
        __nv_bfloat16* ylo = ylos[l & 1];
        wavenet_mma_layer<<<grid, 256, SM_TOTAL>>>(
            xhi, xlo,
            wbf + (size_t)l * 2 * 2 * CHAN * KEFF,
            fb + l * CHAN, gb + l * CHAN,
            yhi, ylo, out, 1 << l, (l == 0) ? 1 : 0);
        xhi = yhi; xlo = ylo;
    }
}

// round 6
// speedup vs baseline: 2.8615x; 1.1901x over previous
#include <cuda_runtime.h>
#include <cuda_fp16.h>
#include <cstdint>
#include <math.h>

#define BATCH 16
#define CHAN  256
#define TLEN  4096
#define NLAYERS 8
#define KEFF  512            // 2 taps * 256 cin stacked
#define NCHUNK 16            // 16 chunks of k=32

// ---------------- device scratch -------------------------------------------
// Activations, [b][t][c] layout, fp16 hi/lo split, ping-pong
__device__ __half g_xhiA[(size_t)BATCH * TLEN * CHAN];
__device__ __half g_xloA[(size_t)BATCH * TLEN * CHAN];
__device__ __half g_xhiB[(size_t)BATCH * TLEN * CHAN];
__device__ __half g_xloB[(size_t)BATCH * TLEN * CHAN];
// Weights: [l][fg][cout][k]  k-major fp16; k<256 -> tap1(current), k>=256 -> tap0
__device__ __half g_w[(size_t)NLAYERS * 2 * CHAN * KEFF];

// ---------------- smem geometry --------------------------------------------
// Per stage: A hi 128 x 80B = 10240, A lo 10240, W 2 fg x 64 x 80B = 10240.
#define AROW   80
#define STAGE_BYTES 30720
#define NSTAGE 3
#define SM_TOTAL (NSTAGE * STAGE_BYTES)   // 92160 (epilogue 64x132 f32 = 33792 reuses it)

// ---------------- asm helpers ----------------------------------------------
__device__ __forceinline__ uint32_t smem_u32(const void* p) {
    uint32_t a;
    asm("{ .reg .u64 t; cvta.to.shared.u64 t, %1; cvt.u32.u64 %0, t; }" : "=r"(a) : "l"(p));
    return a;
}
__device__ __forceinline__ void cp16(uint32_t dst, const void* src, uint32_t srcsize) {
    asm volatile("cp.async.cg.shared.global [%0], [%1], 16, %2;"
                 :: "r"(dst), "l"(src), "r"(srcsize) : "memory");
}
#define CP_COMMIT() asm volatile("cp.async.commit_group;" ::: "memory")
#define CP_WAIT(n)  asm volatile("cp.async.wait_group %0;" :: "n"(n) : "memory")

__device__ __forceinline__ void ldsm4(uint32_t* r, uint32_t addr) {
    asm volatile("ldmatrix.sync.aligned.m8n8.x4.shared.b16 {%0,%1,%2,%3}, [%4];"
                 : "=r"(r[0]), "=r"(r[1]), "=r"(r[2]), "=r"(r[3]) : "r"(addr));
}
__device__ __forceinline__ void mma16816(float* d, const uint32_t* a, const uint32_t* b) {
    asm volatile("mma.sync.aligned.m16n8k16.row.col.f32.f16.f16.f32 "
                 "{%0,%1,%2,%3}, {%4,%5,%6,%7}, {%8,%9}, {%0,%1,%2,%3};"
                 : "+f"(d[0]), "+f"(d[1]), "+f"(d[2]), "+f"(d[3])
                 : "r"(a[0]), "r"(a[1]), "r"(a[2]), "r"(a[3]), "r"(b[0]), "r"(b[1]));
}

// ---------------- prep kernels ---------------------------------------------
__global__ void prep_weights(const float* __restrict__ fw, const float* __restrict__ gw) {
    int idx = blockIdx.x * blockDim.x + threadIdx.x;   // [l][fg][cout][k]
    const int total = NLAYERS * 2 * CHAN * KEFF;
    if (idx >= total) return;
    int k    = idx & (KEFF - 1);
    int cout = (idx >> 9) & (CHAN - 1);
    int fg   = (idx >> 17) & 1;
    int l    = idx >> 18;
    const float* w = fg ? gw : fw;
    int cin = k & (CHAN - 1);
    int tap = (k < CHAN) ? 1 : 0;
    float v = w[(((size_t)l * CHAN + cout) * CHAN + cin) * 2 + tap];
    g_w[idx] = __float2half_rn(v);
}

// [b][c][t] f32 -> [b][t][c] fp16 hi/lo, tiled transpose
__global__ void prep_input(const float* __restrict__ ys) {
    __shared__ float tile[32][33];
    const int b  = blockIdx.z;
    const int c0 = blockIdx.y * 32;
    const int t0 = blockIdx.x * 32;
    const int tx = threadIdx.x, ty = threadIdx.y;   // 32 x 8
#pragma unroll
    for (int i = 0; i < 32; i += 8)
        tile[ty + i][tx] = ys[((size_t)b * CHAN + c0 + ty + i) * TLEN + t0 + tx];
    __syncthreads();
#pragma unroll
    for (int i = 0; i < 32; i += 8) {
        float v = tile[tx][ty + i];
        __half hi = __float2half_rn(v);
        __half lo = __float2half_rn(v - __half2float(hi));
        size_t o = (size_t)b * TLEN * CHAN + (size_t)(t0 + ty + i) * CHAN + c0 + tx;
        g_xhiA[o] = hi;
        g_xloA[o] = lo;
    }
}

// ---------------- per-chunk loader (all cp.async) ---------------------------
__device__ __forceinline__ void load_chunk(
    int c, uint32_t sstage,
    const __half* __restrict__ Xhi, const __half* __restrict__ Xlo,
    const __half* __restrict__ Wl,
    int tid, int t0, int cout0, int dil)
{
    const int shift = (c >= 8) ? dil : 0;
    const int cin0  = (c & 7) * 32;
    // A: 2(hilo) x 128 rows x 4 quads = 1024 cp16
#pragma unroll
    for (int j = 0; j < 4; ++j) {
        int id = tid + j * 256;
        int quad = id & 3, tt = (id >> 2) & 127, hilo = id >> 9;
        int ts = t0 + tt - shift;
        const __half* xb = hilo ? Xlo : Xhi;
        int tsc = ts >= 0 ? ts : 0;
        const __half* src = xb + (size_t)tsc * CHAN + cin0 + quad * 8;
        uint32_t dst = sstage + hilo * 10240 + tt * AROW + quad * 16;
        cp16(dst, src, ts >= 0 ? 16u : 0u);
    }
    // W: 2 fg x 64 rows x 4 quads = 512 cp16
#pragma unroll
    for (int j = 0; j < 2; ++j) {
        int id = tid + j * 256;
        int quad = id & 3, row = (id >> 2) & 63, fg = id >> 8;
        const __half* src = Wl + (size_t)fg * (CHAN * KEFF)
                          + (size_t)(cout0 + row) * KEFF + c * 32 + quad * 8;
        uint32_t dst = sstage + 20480 + fg * 5120 + row * AROW + quad * 16;
        cp16(dst, src, 16u);
    }
}

// ---------------- fused HMMA layer kernel -----------------------------------
__global__ __launch_bounds__(256, 2)
void wavenet_mma_layer(const __half* __restrict__ Xhi,
                       const __half* __restrict__ Xlo,
                       const __half* __restrict__ Wl,
                       const float* __restrict__ fb,
                       const float* __restrict__ gb,
                       __half* __restrict__ Yhi,
                       __half* __restrict__ Ylo,
                       float* __restrict__ Zout,
                       int dil, int first)
{
    extern __shared__ char smem[];
    const uint32_t sb = smem_u32(smem);
    const int tid  = threadIdx.x;
    const int wid  = tid >> 5;
    const int lane = tid & 31;
    const int t0    = blockIdx.x * 128;
    const int cout0 = blockIdx.y * 64;
    const int b     = blockIdx.z;

    const __half* Xh = Xhi + (size_t)b * TLEN * CHAN;
    const __half* Xl = Xlo + (size_t)b * TLEN * CHAN;

    const int m0 = (wid & 3) * 32;   // t within tile
    const int n0 = (wid >> 2) * 32;  // cout within tile

    float accF[2][4][4], accG[2][4][4];
#pragma unroll
    for (int mi = 0; mi < 2; ++mi)
#pragma unroll
        for (int nt = 0; nt < 4; ++nt)
#pragma unroll
            for (int e = 0; e < 4; ++e) { accF[mi][nt][e] = 0.f; accG[mi][nt][e] = 0.f; }

    // prologue: chunks 0,1 -> stages 0,1
    load_chunk(0, sb, Xh, Xl, Wl, tid, t0, cout0, dil);
    CP_COMMIT();
    load_chunk(1, sb + STAGE_BYTES, Xh, Xl, Wl, tid, t0, cout0, dil);
    CP_COMMIT();

    // lane-derived ldmatrix offsets
    const uint32_t a_row = (uint32_t)(lane & 15);
    const uint32_t a_kb  = (uint32_t)((lane >> 4) * 16);
    const uint32_t b_row = (uint32_t)(((lane >> 4) * 8) + (lane & 7));
    const uint32_t b_kb  = (uint32_t)(((lane >> 3) & 1) * 16);

    uint32_t stage_off[NSTAGE] = { 0, STAGE_BYTES, 2 * STAGE_BYTES };
    int scur = 0;

    for (int c = 0; c < NCHUNK; ++c) {
        // issue loads 2 chunks ahead (stage (c+2)%3: its previous tenant was
        // chunk c-1, whose compute all warps finished before the barrier of
        // the previous iteration)
        if (c + 2 < NCHUNK) {
            load_chunk(c + 2, sb + stage_off[(scur + 2) % NSTAGE],
                       Xh, Xl, Wl, tid, t0, cout0, dil);
            CP_COMMIT();
            CP_WAIT(2);
        } else if (c + 1 < NCHUNK) {
            CP_WAIT(1);
        } else {
            CP_WAIT(0);
        }
        __syncthreads();   // everyone's chunk-c loads visible

        const uint32_t sA = sb + stage_off[scur];
        const uint32_t sW = sA + 20480;
#pragma unroll
        for (int ks = 0; ks < 2; ++ks) {
            uint32_t a_hi[2][4], a_lo[2][4], bF[2][4], bG[2][4];
#pragma unroll
            for (int mi = 0; mi < 2; ++mi) {
                uint32_t adr = sA + (m0 + mi * 16 + a_row) * AROW + ks * 32 + a_kb;
                ldsm4(a_hi[mi], adr);
                ldsm4(a_lo[mi], adr + 10240);
            }
#pragma unroll
            for (int nt2 = 0; nt2 < 2; ++nt2) {
                uint32_t off = (n0 + nt2 * 16 + b_row) * AROW + ks * 32 + b_kb;
                ldsm4(bF[nt2], sW + off);
                ldsm4(bG[nt2], sW + 5120 + off);
            }
#pragma unroll
            for (int mi = 0; mi < 2; ++mi)
#pragma unroll
                for (int nt2 = 0; nt2 < 2; ++nt2)
#pragma unroll
                    for (int s = 0; s < 2; ++s) {
                        float* dF = accF[mi][nt2 * 2 + s];
                        float* dG = accG[mi][nt2 * 2 + s];
                        mma16816(dF, a_hi[mi], &bF[nt2][s * 2]);
                        mma16816(dG, a_hi[mi], &bG[nt2][s * 2]);
                        mma16816(dF, a_lo[mi], &bF[nt2][s * 2]);
                        mma16816(dG, a_lo[mi], &bG[nt2][s * 2]);
                    }
        }
        __syncthreads();   // all warps done with stage scur before it is refilled
        scur = (scur + 1) % NSTAGE;
    }

    // ---- epilogue: activation in regs -> z smem tile -> coalesced writeout --
    float* zs = reinterpret_cast<float*>(smem);   // 64 x 132 f32
    {
        const int g  = lane >> 2;
        const int tg = lane & 3;
        float fbv[4][2], gbv[4][2];
#pragma unroll
        for (int nt = 0; nt < 4; ++nt)
#pragma unroll
            for (int p = 0; p < 2; ++p) {
                int cout = cout0 + n0 + nt * 8 + 2 * tg + p;
                fbv[nt][p] = __ldg(fb + cout);
                gbv[nt][p] = __ldg(gb + cout);
            }
#pragma unroll
        for (int mi = 0; mi < 2; ++mi)
#pragma unroll
            for (int nt = 0; nt < 4; ++nt)
#pragma unroll
                for (int e = 0; e < 4; ++e) {
                    int t_loc = m0 + mi * 16 + g + (e >> 1) * 8;
                    int c_loc = n0 + nt * 8 + 2 * tg + (e & 1);
                    float F = accF[mi][nt][e] + fbv[nt][e & 1];
                    float G = accG[mi][nt][e] + gbv[nt][e & 1];
                    float z = tanhf(F) * (0.5f * tanhf(0.5f * G) + 0.5f);
                    zs[c_loc * 132 + t_loc] = z;
                }
    }
    __syncthreads();

    const size_t yb = (size_t)b * TLEN * CHAN;
    const size_t zb = (size_t)b * CHAN * TLEN;
    // Y: [b][t][c] fp16 hi/lo, lanes walk c
#pragma unroll
    for (int i = 0; i < 32; ++i) {
        int id = tid + i * 256;
        int cl = id & 63, t = id >> 6;
        float z = zs[cl * 132 + t];
        __half h = __float2half_rn(z);
        __half l = __float2half_rn(z - __half2float(h));
        size_t o = yb + (size_t)(t0 + t) * CHAN + cout0 + cl;
        Yhi[o] = h;
        Ylo[o] = l;
    }
    // Zout: [b][c][t] f32, lanes walk t
#pragma unroll
    for (int i = 0; i < 32; ++i) {
        int id = tid + i * 256;
        int t = id & 127, cl = id >> 7;
        float z = zs[cl * 132 + t];
        size_t o = zb + (size_t)(cout0 + cl) * TLEN + t0 + t;
        if (first) Zout[o] = z;
        else       Zout[o] += z;
    }
}

// ---------------- launch ----------------------------------------------------
extern "C" void kernel_launch(void* const* d_in, const int* in_sizes, int n_in,
                              void* d_out, int out_size) {
    const float* ys = (const float*)d_in[0];
    const float* fw = (const float*)d_in[1];
    const float* fb = (const float*)d_in[2];
    const float* gw = (const float*)d_in[3];
    const float* gb = (const float*)d_in[4];
    float* out = (float*)d_out;

    __half *xhiA, *xloA, *xhiB, *xloB, *wh;
    cudaGetSymbolAddress((void**)&xhiA, g_xhiA);
    cudaGetSymbolAddress((void**)&xloA, g_xloA);
    cudaGetSymbolAddress((void**)&xhiB, g_xhiB);
    cudaGetSymbolAddress((void**)&xloB, g_xloB);
    cudaGetSymbolAddress((void**)&wh,   g_w);

    static int attr_done = 0;
    if (!attr_done) {
        cudaFuncSetAttribute(wavenet_mma_layer,
                             cudaFuncAttributeMaxDynamicSharedMemorySize, SM_TOTAL);
        attr_done = 1;
    }

    {
        const int total = NLAYERS * 2 * CHAN * KEFF;
        prep_weights<<<(total + 255) / 256, 256>>>(fw, gw);
        dim3 tg(TLEN / 32, CHAN / 32, BATCH);
        prep_input<<<tg, dim3(32, 8)>>>(ys);
    }

    dim3 grid(TLEN / 128, CHAN / 64, BATCH);
    const __half* xhi = xhiA;
    const __half* xlo = xloA;
    __half* yhis[2] = { xhiB, xhiA };
    __half* ylos[2] = { xloB, xloA };
    for (int l = 0; l < NLAYERS; ++l) {
        __half* yhi = yhis[l & 1];
        __half* ylo = ylos[l & 1];
        wavenet_mma_layer<<<grid, 256, SM_TOTAL>>>(
            xhi, xlo,
            wh + (size_t)l * 2 * CHAN * KEFF,
            fb + l * CHAN, gb + l * CHAN,
            yhi, ylo, out, 1 << l, (l == 0) ? 1 : 0);
        xhi = yhi; xlo = ylo;
    }
}

// round 7
// speedup vs baseline: 3.6190x; 1.2647x over previous
#include <cuda_runtime.h>
#include <cuda_fp16.h>
#include <cstdint>
#include <math.h>

#define BATCH 16
#define CHAN  256
#define TLEN  4096
#define NLAYERS 8
#define NCHUNK 16
#define GUARD 128
#define PROWS (GUARD + TLEN)            // 4224 rows per plane
#define PLANE ((size_t)PROWS * 32)      // halfs per (b,kc) plane
#define XBUF  ((size_t)BATCH * 8 * PLANE)

// ---------------- device scratch -------------------------------------------
// X planes: [b][kc][GUARD+t][32ch], quad-swizzled, fp16 hi/lo, ping-pong
__device__ __align__(128) __half g_xhiA[XBUF];
__device__ __align__(128) __half g_xloA[XBUF];
__device__ __align__(128) __half g_xhiB[XBUF];
__device__ __align__(128) __half g_xloB[XBUF];
// W: [l][fg][chunk16][cout256][32k], quad-swizzled by cout
__device__ __align__(128) __half g_w2[(size_t)NLAYERS * 2 * 16 * 256 * 32];

// ---------------- smem geometry --------------------------------------------
// Stage: A hi 128x64B=8192 | A lo 8192 | Wf 64x64B=4096 | Wg 4096  = 24576
#define STAGE_BYTES 24576
#define STAGE_TX    24576
#define NSTAGE 3
#define MB_OFF (NSTAGE * STAGE_BYTES)      // 73728
#define SM_TOTAL (MB_OFF + 64)

// ---------------- asm helpers ----------------------------------------------
__device__ __forceinline__ uint32_t smem_u32(const void* p) {
    uint32_t a;
    asm("{ .reg .u64 t; cvta.to.shared.u64 t, %1; cvt.u32.u64 %0, t; }" : "=r"(a) : "l"(p));
    return a;
}
#define MBARRIER_INIT(mbar, cnt) \
    asm volatile("mbarrier.init.shared.b64 [%0], %1;" :: "r"((uint32_t)(mbar)), "r"((uint32_t)(cnt)) : "memory")
#define MBARRIER_EXPECT_TX(mbar, tx) \
    asm volatile("mbarrier.arrive.expect_tx.shared.b64 _, [%0], %1;" :: "r"((uint32_t)(mbar)), "r"((uint32_t)(tx)) : "memory")
#define FENCE_ASYNC() asm volatile("fence.proxy.async.shared::cta;" ::: "memory")
#define MBARRIER_WAIT_PARITY(mbar, par) do { \
    uint32_t _m = (uint32_t)(mbar); uint32_t _p = (uint32_t)(par); uint32_t _d; \
    asm volatile("{\n\t.reg .pred p;\n\tmbarrier.try_wait.parity.acquire.cta.shared::cta.b64 p, [%1], %2;\n\tselp.b32 %0,1,0,p;\n\t}" \
        : "=r"(_d) : "r"(_m), "r"(_p) : "memory"); \
    if (!_d) { \
        asm volatile("{\n\t.reg .pred P1;\n\tWL_%=:\n\tmbarrier.try_wait.parity.acquire.cta.shared::cta.b64 P1, [%0], %1, 0x989680;\n\t@P1 bra.uni WD_%=;\n\tbra.uni WL_%=;\n\tWD_%=:\n\t}" \
            :: "r"(_m), "r"(_p) : "memory"); \
    } } while (0)
__device__ __forceinline__ void bulk_ld(uint32_t dst, const void* src, uint32_t bytes, uint32_t mbar) {
    asm volatile("cp.async.bulk.shared::cluster.global.mbarrier::complete_tx::bytes [%0], [%1], %2, [%3];"
                 :: "r"(dst), "l"(src), "r"(bytes), "r"(mbar) : "memory");
}
__device__ __forceinline__ void ldsm4(uint32_t* r, uint32_t addr) {
    asm volatile("ldmatrix.sync.aligned.m8n8.x4.shared.b16 {%0,%1,%2,%3}, [%4];"
                 : "=r"(r[0]), "=r"(r[1]), "=r"(r[2]), "=r"(r[3]) : "r"(addr));
}
__device__ __forceinline__ void mma16816(float* d, const uint32_t* a, const uint32_t* b) {
    asm volatile("mma.sync.aligned.m16n8k16.row.col.f32.f16.f16.f32 "
                 "{%0,%1,%2,%3}, {%4,%5,%6,%7}, {%8,%9}, {%0,%1,%2,%3};"
                 : "+f"(d[0]), "+f"(d[1]), "+f"(d[2]), "+f"(d[3])
                 : "r"(a[0]), "r"(a[1]), "r"(a[2]), "r"(a[3]), "r"(b[0]), "r"(b[1]));
}

// ---------------- prep kernels ---------------------------------------------
__global__ void zero_guards() {
    const size_t per = (size_t)BATCH * 8 * GUARD * 32;    // 524288
    size_t i = (size_t)blockIdx.x * blockDim.x + threadIdx.x;
    if (i >= 4 * per) return;
    int arr = (int)(i / per);
    size_t r = i % per;
    size_t plane_i = r / (GUARD * 32);
    size_t within  = r % (GUARD * 32);
    __half* p;
    if      (arr == 0) p = g_xhiA;
    else if (arr == 1) p = g_xloA;
    else if (arr == 2) p = g_xhiB;
    else               p = g_xloB;
    p[plane_i * PLANE + within] = __ushort_as_half(0);
}

// w[l][cout][cin][tap] -> g_w2[l][fg][chunk][cout][32k] with quad swizzle by cout
__global__ void prep_weights(const float* __restrict__ fw, const float* __restrict__ gw) {
    int idx = blockIdx.x * blockDim.x + threadIdx.x;
    const int total = NLAYERS * 2 * 16 * 256 * 32;
    if (idx >= total) return;
    int kk   = idx & 31;
    int cout = (idx >> 5) & 255;
    int ch   = (idx >> 13) & 15;
    int fg   = (idx >> 17) & 1;
    int l    = idx >> 18;
    const float* w = fg ? gw : fw;
    int cin = (ch & 7) * 32 + kk;
    int tap = (ch < 8) ? 1 : 0;    // first 8 chunks = current sample
    float v = w[(((size_t)l * CHAN + cout) * CHAN + cin) * 2 + tap];
    int pos = (((kk >> 3) ^ ((cout >> 1) & 3)) << 3) | (kk & 7);
    g_w2[((((size_t)l * 2 + fg) * 16 + ch) * 256 + cout) * 32 + pos] = __float2half_rn(v);
}

// ys [b][c][t] f32 -> swizzled planes, hi/lo fp16
__global__ void prep_input(const float* __restrict__ ys) {
    __shared__ float tile[32][33];
    const int b  = blockIdx.z;
    const int c0 = blockIdx.y * 32;
    const int t0 = blockIdx.x * 32;
    const int tx = threadIdx.x, ty = threadIdx.y;   // 32 x 8
#pragma unroll
    for (int i = 0; i < 32; i += 8)
        tile[ty + i][tx] = ys[((size_t)b * CHAN + c0 + ty + i) * TLEN + t0 + tx];
    __syncthreads();
    const int kc = c0 >> 5;
#pragma unroll
    for (int i = 0; i < 32; i += 8) {
        int t = t0 + ty + i;
        float v = tile[tx][ty + i];
        __half hi = __float2half_rn(v);
        __half lo = __float2half_rn(v - __half2float(hi));
        int pos = (((tx >> 3) ^ ((t >> 1) & 3)) << 3) | (tx & 7);
        size_t o = (((size_t)b * 8 + kc) * PROWS + GUARD + t) * 32 + pos;
        g_xhiA[o] = hi;
        g_xloA[o] = lo;
    }
}

// ---------------- fused HMMA layer kernel (bulk-loaded) ----------------------
__global__ __launch_bounds__(256, 2)
void wavenet_mma_layer(const __half* __restrict__ Xhi,
                       const __half* __restrict__ Xlo,
                       const __half* __restrict__ Wl,   // [fg][chunk][256][32]
                       const float* __restrict__ fb,
                       const float* __restrict__ gb,
                       __half* __restrict__ Yhi,
                       __half* __restrict__ Ylo,
                       float* __restrict__ Zout,
                       int dil, int first)
{
    extern __shared__ char smem[];
    const uint32_t sb = smem_u32(smem);
    const int tid  = threadIdx.x;
    const int wid  = tid >> 5;
    const int lane = tid & 31;
    const int t0    = blockIdx.x * 128;
    const int cout0 = blockIdx.y * 64;
    const int b     = blockIdx.z;

    const __half* Xh = Xhi + (size_t)b * 8 * PLANE;
    const __half* Xl = Xlo + (size_t)b * 8 * PLANE;

    const int m0 = (wid & 3) * 32;
    const int n0 = (wid >> 2) * 32;

    float accF[2][4][4], accG[2][4][4];
#pragma unroll
    for (int mi = 0; mi < 2; ++mi)
#pragma unroll
        for (int nt = 0; nt < 4; ++nt)
#pragma unroll
            for (int e = 0; e < 4; ++e) { accF[mi][nt][e] = 0.f; accG[mi][nt][e] = 0.f; }

    if (tid == 0) {
        MBARRIER_INIT(sb + MB_OFF + 0, 1);
        MBARRIER_INIT(sb + MB_OFF + 8, 1);
        MBARRIER_INIT(sb + MB_OFF + 16, 1);
    }
    __syncthreads();

#define ISSUE_CHUNK(C, S) do {                                                   \
        uint32_t _mb = sb + MB_OFF + (S) * 8;                                    \
        uint32_t _st = sb + (S) * STAGE_BYTES;                                   \
        int _sh = ((C) >= 8) ? dil : 0;                                          \
        int _kc = (C) & 7;                                                       \
        MBARRIER_EXPECT_TX(_mb, STAGE_TX);                                       \
        bulk_ld(_st,         Xh + ((size_t)_kc * PROWS + GUARD + t0 - _sh) * 32, 8192, _mb); \
        bulk_ld(_st + 8192,  Xl + ((size_t)_kc * PROWS + GUARD + t0 - _sh) * 32, 8192, _mb); \
        bulk_ld(_st + 16384, Wl + ((size_t)(0  + (C)) * 256 + cout0) * 32, 4096, _mb); \
        bulk_ld(_st + 20480, Wl + ((size_t)(16 + (C)) * 256 + cout0) * 32, 4096, _mb); \
    } while (0)

    if (tid == 0) {
        FENCE_ASYNC();
        ISSUE_CHUNK(0, 0);
        ISSUE_CHUNK(1, 1);
    }

    const uint32_t a_row = (uint32_t)(lane & 15);
    const uint32_t a_q0  = (uint32_t)(lane >> 4);          // 0/1
    const uint32_t b_row = (uint32_t)(((lane >> 4) * 8) + (lane & 7));
    const uint32_t b_q0  = (uint32_t)((lane >> 3) & 1);    // 0/1
    const uint32_t bkey  = ((n0 + b_row) >> 1) & 3;

    for (int c = 0; c < NCHUNK; ++c) {
        const int s = c % 3;
        MBARRIER_WAIT_PARITY(sb + MB_OFF + s * 8, (c / 3) & 1);

        const int shift = (c >= 8) ? dil : 0;
        const uint32_t sA = sb + s * STAGE_BYTES;
        const uint32_t sW = sA + 16384;
        const uint32_t akey = (uint32_t)((t0 + m0 + (int)a_row - shift + 8192) >> 1) & 3;

#pragma unroll
        for (int ks = 0; ks < 2; ++ks) {
            uint32_t a_hi[2][4], a_lo[2][4], bF[2][4], bG[2][4];
            const uint32_t qa = ((ks * 2 + a_q0) ^ akey) * 16;
            const uint32_t qb = ((ks * 2 + b_q0) ^ bkey) * 16;
#pragma unroll
            for (int mi = 0; mi < 2; ++mi) {
                uint32_t adr = sA + (m0 + mi * 16 + a_row) * 64 + qa;
                ldsm4(a_hi[mi], adr);
                ldsm4(a_lo[mi], adr + 8192);
            }
#pragma unroll
            for (int nt2 = 0; nt2 < 2; ++nt2) {
                uint32_t adr = sW + (n0 + nt2 * 16 + b_row) * 64 + qb;
                ldsm4(bF[nt2], adr);
                ldsm4(bG[nt2], adr + 4096);
            }
#pragma unroll
            for (int mi = 0; mi < 2; ++mi)
#pragma unroll
                for (int nt2 = 0; nt2 < 2; ++nt2)
#pragma unroll
                    for (int sN = 0; sN < 2; ++sN) {
                        float* dF = accF[mi][nt2 * 2 + sN];
                        float* dG = accG[mi][nt2 * 2 + sN];
                        mma16816(dF, a_hi[mi], &bF[nt2][sN * 2]);
                        mma16816(dG, a_hi[mi], &bG[nt2][sN * 2]);
                        mma16816(dF, a_lo[mi], &bF[nt2][sN * 2]);
                        mma16816(dG, a_lo[mi], &bG[nt2][sN * 2]);
                    }
        }
        __syncthreads();   // all warps done with stage s (and stage (c+2)%3's old data)
        if (tid == 0 && c + 2 < NCHUNK) {
            FENCE_ASYNC();
            ISSUE_CHUNK(c + 2, (c + 2) % 3);
        }
    }
#undef ISSUE_CHUNK

    // ---- epilogue: z tile [t][c] (stride 68), then coalesced writeout -------
    float* zs = reinterpret_cast<float*>(smem);   // 128 x 68 f32 = 34816 B
    {
        const int g  = lane >> 2;
        const int tg = lane & 3;
        float fbv[4][2], gbv[4][2];
#pragma unroll
        for (int nt = 0; nt < 4; ++nt)
#pragma unroll
            for (int p = 0; p < 2; ++p) {
                int cout = cout0 + n0 + nt * 8 + 2 * tg + p;
                fbv[nt][p] = __ldg(fb + cout);
                gbv[nt][p] = __ldg(gb + cout);
            }
#pragma unroll
        for (int mi = 0; mi < 2; ++mi)
#pragma unroll
            for (int nt = 0; nt < 4; ++nt)
#pragma unroll
                for (int e = 0; e < 4; ++e) {
                    int t_loc = m0 + mi * 16 + g + (e >> 1) * 8;
                    int c_loc = n0 + nt * 8 + 2 * tg + (e & 1);
                    float F = accF[mi][nt][e] + fbv[nt][e & 1];
                    float G = accG[mi][nt][e] + gbv[nt][e & 1];
                    float z = tanhf(F) * (0.5f * tanhf(0.5f * G) + 0.5f);
                    zs[t_loc * 68 + c_loc] = z;
                }
    }
    __syncthreads();

    // Y planes: quad-granular stores, swizzled
#pragma unroll
    for (int i = 0; i < 8; ++i) {
        int id = tid + i * 256;
        int q8 = id & 7, t = (id >> 3) & 127, hilo = id >> 10;
        const float* zr = zs + t * 68 + q8 * 8;
        float4 z0 = reinterpret_cast<const float4*>(zr)[0];
        float4 z1 = reinterpret_cast<const float4*>(zr)[1];
        float zv[8] = { z0.x, z0.y, z0.z, z0.w, z1.x, z1.y, z1.z, z1.w };
        uint32_t pk[4];
#pragma unroll
        for (int p = 0; p < 4; ++p) {
            __half h0 = __float2half_rn(zv[2 * p]);
            __half h1 = __float2half_rn(zv[2 * p + 1]);
            if (hilo) {
                h0 = __float2half_rn(zv[2 * p]     - __half2float(h0));
                h1 = __float2half_rn(zv[2 * p + 1] - __half2float(h1));
            }
            pk[p] = (uint32_t)__half_as_ushort(h0) | ((uint32_t)__half_as_ushort(h1) << 16);
        }
        int cg = cout0 + q8 * 8;
        int kc = cg >> 5;
        int tgl = t0 + t;
        int swq = ((cg >> 3) & 3) ^ ((tgl >> 1) & 3);
        __half* dst = (hilo ? Ylo : Yhi) + (((size_t)b * 8 + kc) * PROWS + GUARD + tgl) * 32 + swq * 8;
        *reinterpret_cast<uint4*>(dst) = make_uint4(pk[0], pk[1], pk[2], pk[3]);
    }
    // Zout: [b][c][t] f32
    const size_t zb = (size_t)b * CHAN * TLEN;
#pragma unroll
    for (int i = 0; i < 32; ++i) {
        int id = tid + i * 256;
        int t = id & 127, cl = id >> 7;
        float z = zs[t * 68 + cl];
        size_t o = zb + (size_t)(cout0 + cl) * TLEN + t0 + t;
        if (first) Zout[o] = z;
        else       Zout[o] += z;
    }
}

// ---------------- launch ----------------------------------------------------
extern "C" void kernel_launch(void* const* d_in, const int* in_sizes, int n_in,
                              void* d_out, int out_size) {
    const float* ys = (const float*)d_in[0];
    const float* fw = (const float*)d_in[1];
    const float* fb = (const float*)d_in[2];
    const float* gw = (const float*)d_in[3];
    const float* gb = (const float*)d_in[4];
    float* out = (float*)d_out;

    __half *xhiA, *xloA, *xhiB, *xloB, *wh;
    cudaGetSymbolAddress((void**)&xhiA, g_xhiA);
    cudaGetSymbolAddress((void**)&xloA, g_xloA);
    cudaGetSymbolAddress((void**)&xhiB, g_xhiB);
    cudaGetSymbolAddress((void**)&xloB, g_xloB);
    cudaGetSymbolAddress((void**)&wh,   g_w2);

    static int attr_done = 0;
    if (!attr_done) {
        cudaFuncSetAttribute(wavenet_mma_layer,
                             cudaFuncAttributeMaxDynamicSharedMemorySize, SM_TOTAL);
        attr_done = 1;
    }

    {
        const size_t gz = (size_t)4 * BATCH * 8 * GUARD * 32;
        zero_guards<<<(int)((gz + 255) / 256), 256>>>();
        const int total = NLAYERS * 2 * 16 * 256 * 32;
        prep_weights<<<(total + 255) / 256, 256>>>(fw, gw);
        dim3 tg(TLEN / 32, CHAN / 32, BATCH);
        prep_input<<<tg, dim3(32, 8)>>>(ys);
    }

    dim3 grid(TLEN / 128, CHAN / 64, BATCH);
    const __half* xhi = xhiA;
    const __half* xlo = xloA;
    __half* yhis[2] = { xhiB, xhiA };
    __half* ylos[2] = { xloB, xloA };
    for (int l = 0; l < NLAYERS; ++l) {
        __half* yhi = yhis[l & 1];
        __half* ylo = ylos[l & 1];
        wavenet_mma_layer<<<grid, 256, SM_TOTAL>>>(
            xhi, xlo,
            wh + (size_t)l * 2 * 16 * 256 * 32,
            fb + l * CHAN, gb + l * CHAN,
            yhi, ylo, out, 1 << l, (l == 0) ? 1 : 0);
        xhi = yhi; xlo = ylo;
    }
}

// round 8
// speedup vs baseline: 4.5117x; 1.2467x over previous
#include <cuda_runtime.h>
#include <cuda_fp16.h>
#include <cstdint>
#include <math.h>

#define BATCH 16
#define CHAN  256
#define TLEN  4096
#define NLAYERS 8
#define NCHUNK 16
#define GUARD 128
#define PROWS (GUARD + TLEN)            // 4224 rows per plane
#define PLANE ((size_t)PROWS * 32)      // halfs per (b,kc) plane
#define XBUF  ((size_t)BATCH * 8 * PLANE)

// ---------------- device scratch -------------------------------------------
// X planes: [b][kc][GUARD+t][32ch], quad-swizzled, fp16, ping-pong
__device__ __align__(128) __half g_xA[XBUF];
__device__ __align__(128) __half g_xB[XBUF];
// W: [l][fg][chunk16][cout256][32k], quad-swizzled by cout
__device__ __align__(128) __half g_w2[(size_t)NLAYERS * 2 * 16 * 256 * 32];

// ---------------- smem geometry --------------------------------------------
// Stage: A 128x64B=8192 | Wf 64x64B=4096 | Wg 4096  = 16384
#define STAGE_BYTES 16384
#define STAGE_TX    16384
#define NSTAGE 4
#define MB_OFF (NSTAGE * STAGE_BYTES)      // 65536
#define SM_TOTAL (MB_OFF + 64)

// ---------------- asm helpers ----------------------------------------------
__device__ __forceinline__ uint32_t smem_u32(const void* p) {
    uint32_t a;
    asm("{ .reg .u64 t; cvta.to.shared.u64 t, %1; cvt.u32.u64 %0, t; }" : "=r"(a) : "l"(p));
    return a;
}
#define MBARRIER_INIT(mbar, cnt) \
    asm volatile("mbarrier.init.shared.b64 [%0], %1;" :: "r"((uint32_t)(mbar)), "r"((uint32_t)(cnt)) : "memory")
#define MBARRIER_EXPECT_TX(mbar, tx) \
    asm volatile("mbarrier.arrive.expect_tx.shared.b64 _, [%0], %1;" :: "r"((uint32_t)(mbar)), "r"((uint32_t)(tx)) : "memory")
#define FENCE_ASYNC() asm volatile("fence.proxy.async.shared::cta;" ::: "memory")
#define MBARRIER_WAIT_PARITY(mbar, par) do { \
    uint32_t _m = (uint32_t)(mbar); uint32_t _p = (uint32_t)(par); uint32_t _d; \
    asm volatile("{\n\t.reg .pred p;\n\tmbarrier.try_wait.parity.acquire.cta.shared::cta.b64 p, [%1], %2;\n\tselp.b32 %0,1,0,p;\n\t}" \
        : "=r"(_d) : "r"(_m), "r"(_p) : "memory"); \
    if (!_d) { \
        asm volatile("{\n\t.reg .pred P1;\n\tWL_%=:\n\tmbarrier.try_wait.parity.acquire.cta.shared::cta.b64 P1, [%0], %1, 0x989680;\n\t@P1 bra.uni WD_%=;\n\tbra.uni WL_%=;\n\tWD_%=:\n\t}" \
            :: "r"(_m), "r"(_p) : "memory"); \
    } } while (0)
__device__ __forceinline__ void bulk_ld(uint32_t dst, const void* src, uint32_t bytes, uint32_t mbar) {
    asm volatile("cp.async.bulk.shared::cluster.global.mbarrier::complete_tx::bytes [%0], [%1], %2, [%3];"
                 :: "r"(dst), "l"(src), "r"(bytes), "r"(mbar) : "memory");
}
__device__ __forceinline__ void ldsm4(uint32_t* r, uint32_t addr) {
    asm volatile("ldmatrix.sync.aligned.m8n8.x4.shared.b16 {%0,%1,%2,%3}, [%4];"
                 : "=r"(r[0]), "=r"(r[1]), "=r"(r[2]), "=r"(r[3]) : "r"(addr));
}
__device__ __forceinline__ void mma16816(float* d, const uint32_t* a, const uint32_t* b) {
    asm volatile("mma.sync.aligned.m16n8k16.row.col.f32.f16.f16.f32 "
                 "{%0,%1,%2,%3}, {%4,%5,%6,%7}, {%8,%9}, {%0,%1,%2,%3};"
                 : "+f"(d[0]), "+f"(d[1]), "+f"(d[2]), "+f"(d[3])
                 : "r"(a[0]), "r"(a[1]), "r"(a[2]), "r"(a[3]), "r"(b[0]), "r"(b[1]));
}

// ---------------- prep kernels ---------------------------------------------
__global__ void zero_guards() {
    const size_t per = (size_t)BATCH * 8 * GUARD * 32;    // 524288
    size_t i = (size_t)blockIdx.x * blockDim.x + threadIdx.x;
    if (i >= 2 * per) return;
    int arr = (int)(i / per);
    size_t r = i % per;
    size_t plane_i = r / (GUARD * 32);
    size_t within  = r % (GUARD * 32);
    __half* p = arr ? g_xB : g_xA;
    p[plane_i * PLANE + within] = __ushort_as_half(0);
}

// w[l][cout][cin][tap] -> g_w2[l][fg][chunk][cout][32k] with quad swizzle by cout
__global__ void prep_weights(const float* __restrict__ fw, const float* __restrict__ gw) {
    int idx = blockIdx.x * blockDim.x + threadIdx.x;
    const int total = NLAYERS * 2 * 16 * 256 * 32;
    if (idx >= total) return;
    int kk   = idx & 31;
    int cout = (idx >> 5) & 255;
    int ch   = (idx >> 13) & 15;
    int fg   = (idx >> 17) & 1;
    int l    = idx >> 18;
    const float* w = fg ? gw : fw;
    int cin = (ch & 7) * 32 + kk;
    int tap = (ch < 8) ? 1 : 0;    // first 8 chunks = current sample
    float v = w[(((size_t)l * CHAN + cout) * CHAN + cin) * 2 + tap];
    int pos = (((kk >> 3) ^ ((cout >> 1) & 3)) << 3) | (kk & 7);
    g_w2[((((size_t)l * 2 + fg) * 16 + ch) * 256 + cout) * 32 + pos] = __float2half_rn(v);
}

// ys [b][c][t] f32 -> swizzled planes, fp16
__global__ void prep_input(const float* __restrict__ ys) {
    __shared__ float tile[32][33];
    const int b  = blockIdx.z;
    const int c0 = blockIdx.y * 32;
    const int t0 = blockIdx.x * 32;
    const int tx = threadIdx.x, ty = threadIdx.y;   // 32 x 8
#pragma unroll
    for (int i = 0; i < 32; i += 8)
        tile[ty + i][tx] = ys[((size_t)b * CHAN + c0 + ty + i) * TLEN + t0 + tx];
    __syncthreads();
    const int kc = c0 >> 5;
#pragma unroll
    for (int i = 0; i < 32; i += 8) {
        int t = t0 + ty + i;
        int pos = (((tx >> 3) ^ ((t >> 1) & 3)) << 3) | (tx & 7);
        size_t o = (((size_t)b * 8 + kc) * PROWS + GUARD + t) * 32 + pos;
        g_xA[o] = __float2half_rn(tile[tx][ty + i]);
    }
}

// ---------------- fused HMMA layer kernel (bulk-loaded) ----------------------
__global__ __launch_bounds__(256, 2)
void wavenet_mma_layer(const __half* __restrict__ X,
                       const __half* __restrict__ Wl,   // [fg][chunk][256][32]
                       const float* __restrict__ fb,
                       const float* __restrict__ gb,
                       __half* __restrict__ Y,
                       float* __restrict__ Zout,
                       int dil, int first)
{
    extern __shared__ char smem[];
    const uint32_t sb = smem_u32(smem);
    const int tid  = threadIdx.x;
    const int wid  = tid >> 5;
    const int lane = tid & 31;
    const int t0    = blockIdx.x * 128;
    const int cout0 = blockIdx.y * 64;
    const int b     = blockIdx.z;

    const __half* Xb = X + (size_t)b * 8 * PLANE;

    const int m0 = (wid & 3) * 32;
    const int n0 = (wid >> 2) * 32;

    float accF[2][4][4], accG[2][4][4];
#pragma unroll
    for (int mi = 0; mi < 2; ++mi)
#pragma unroll
        for (int nt = 0; nt < 4; ++nt)
#pragma unroll
            for (int e = 0; e < 4; ++e) { accF[mi][nt][e] = 0.f; accG[mi][nt][e] = 0.f; }

    if (tid < NSTAGE * 8 && (tid & 7) == 0)
        MBARRIER_INIT(sb + MB_OFF + tid, 1);
    __syncthreads();

#define ISSUE_CHUNK(C, S) do {                                                   \
        uint32_t _mb = sb + MB_OFF + (S) * 8;                                    \
        uint32_t _st = sb + (S) * STAGE_BYTES;                                   \
        int _sh = ((C) >= 8) ? dil : 0;                                          \
        int _kc = (C) & 7;                                                       \
        MBARRIER_EXPECT_TX(_mb, STAGE_TX);                                       \
        bulk_ld(_st,         Xb + ((size_t)_kc * PROWS + GUARD + t0 - _sh) * 32, 8192, _mb); \
        bulk_ld(_st + 8192,  Wl + ((size_t)(0  + (C)) * 256 + cout0) * 32, 4096, _mb); \
        bulk_ld(_st + 12288, Wl + ((size_t)(16 + (C)) * 256 + cout0) * 32, 4096, _mb); \
    } while (0)

    if (tid == 0) {
        FENCE_ASYNC();
        ISSUE_CHUNK(0, 0);
        ISSUE_CHUNK(1, 1);
        ISSUE_CHUNK(2, 2);
    }

    const uint32_t a_row = (uint32_t)(lane & 15);
    const uint32_t a_q0  = (uint32_t)(lane >> 4);          // 0/1
    const uint32_t b_row = (uint32_t)(((lane >> 4) * 8) + (lane & 7));
    const uint32_t b_q0  = (uint32_t)((lane >> 3) & 1);    // 0/1
    const uint32_t bkey  = ((n0 + b_row) >> 1) & 3;

    for (int c = 0; c < NCHUNK; ++c) {
        const int s = c & 3;
        MBARRIER_WAIT_PARITY(sb + MB_OFF + s * 8, (c >> 2) & 1);

        const int shift = (c >= 8) ? dil : 0;
        const uint32_t sA = sb + s * STAGE_BYTES;
        const uint32_t sW = sA + 8192;
        const uint32_t akey = (uint32_t)((t0 + m0 + (int)a_row - shift + 8192) >> 1) & 3;

#pragma unroll
        for (int ks = 0; ks < 2; ++ks) {
            uint32_t a[2][4], bF[2][4], bG[2][4];
            const uint32_t qa = ((ks * 2 + a_q0) ^ akey) * 16;
            const uint32_t qb = ((ks * 2 + b_q0) ^ bkey) * 16;
#pragma unroll
            for (int mi = 0; mi < 2; ++mi)
                ldsm4(a[mi], sA + (m0 + mi * 16 + a_row) * 64 + qa);
#pragma unroll
            for (int nt2 = 0; nt2 < 2; ++nt2) {
                uint32_t adr = sW + (n0 + nt2 * 16 + b_row) * 64 + qb;
                ldsm4(bF[nt2], adr);
                ldsm4(bG[nt2], adr + 4096);
            }
#pragma unroll
            for (int mi = 0; mi < 2; ++mi)
#pragma unroll
                for (int nt2 = 0; nt2 < 2; ++nt2)
#pragma unroll
                    for (int sN = 0; sN < 2; ++sN) {
                        mma16816(accF[mi][nt2 * 2 + sN], a[mi], &bF[nt2][sN * 2]);
                        mma16816(accG[mi][nt2 * 2 + sN], a[mi], &bG[nt2][sN * 2]);
                    }
        }
        __syncthreads();   // all warps done with stage s before stage (c+3)&3 refill
        if (tid == 0 && c + 3 < NCHUNK) {
            FENCE_ASYNC();
            ISSUE_CHUNK(c + 3, (c + 3) & 3);
        }
    }
#undef ISSUE_CHUNK

    // ---- epilogue: z tile [t][c] (stride 68), then coalesced writeout -------
    float* zs = reinterpret_cast<float*>(smem);   // 128 x 68 f32 = 34816 B
    {
        const int g  = lane >> 2;
        const int tg = lane & 3;
        float fbv[4][2], gbv[4][2];
#pragma unroll
        for (int nt = 0; nt < 4; ++nt)
#pragma unroll
            for (int p = 0; p < 2; ++p) {
                int cout = cout0 + n0 + nt * 8 + 2 * tg + p;
                fbv[nt][p] = __ldg(fb + cout);
                gbv[nt][p] = __ldg(gb + cout);
            }
#pragma unroll
        for (int mi = 0; mi < 2; ++mi)
#pragma unroll
            for (int nt = 0; nt < 4; ++nt)
#pragma unroll
                for (int e = 0; e < 4; ++e) {
                    int t_loc = m0 + mi * 16 + g + (e >> 1) * 8;
                    int c_loc = n0 + nt * 8 + 2 * tg + (e & 1);
                    float F = accF[mi][nt][e] + fbv[nt][e & 1];
                    float G = accG[mi][nt][e] + gbv[nt][e & 1];
                    float z = tanhf(F) * (0.5f * tanhf(0.5f * G) + 0.5f);
                    zs[t_loc * 68 + c_loc] = z;
                }
    }
    __syncthreads();

    // Y planes: quad-granular stores, swizzled
#pragma unroll
    for (int i = 0; i < 4; ++i) {
        int id = tid + i * 256;
        int q8 = id & 7, t = (id >> 3) & 127;
        const float* zr = zs + t * 68 + q8 * 8;
        float4 z0 = reinterpret_cast<const float4*>(zr)[0];
        float4 z1 = reinterpret_cast<const float4*>(zr)[1];
        float zv[8] = { z0.x, z0.y, z0.z, z0.w, z1.x, z1.y, z1.z, z1.w };
        uint32_t pk[4];
#pragma unroll
        for (int p = 0; p < 4; ++p) {
            __half h0 = __float2half_rn(zv[2 * p]);
            __half h1 = __float2half_rn(zv[2 * p + 1]);
            pk[p] = (uint32_t)__half_as_ushort(h0) | ((uint32_t)__half_as_ushort(h1) << 16);
        }
        int cg = cout0 + q8 * 8;
        int kc = cg >> 5;
        int tgl = t0 + t;
        int swq = ((cg >> 3) & 3) ^ ((tgl >> 1) & 3);
        __half* dst = Y + (((size_t)b * 8 + kc) * PROWS + GUARD + tgl) * 32 + swq * 8;
        *reinterpret_cast<uint4*>(dst) = make_uint4(pk[0], pk[1], pk[2], pk[3]);
    }
    // Zout: [b][c][t] f32
    const size_t zb = (size_t)b * CHAN * TLEN;
#pragma unroll
    for (int i = 0; i < 32; ++i) {
        int id = tid + i * 256;
        int t = id & 127, cl = id >> 7;
        float z = zs[t * 68 + cl];
        size_t o = zb + (size_t)(cout0 + cl) * TLEN + t0 + t;
        if (first) Zout[o] = z;
        else       Zout[o] += z;
    }
}

// ---------------- launch ----------------------------------------------------
extern "C" void kernel_launch(void* const* d_in, const int* in_sizes, int n_in,
                              void* d_out, int out_size) {
    const float* ys = (const float*)d_in[0];
    const float* fw = (const float*)d_in[1];
    const float* fb = (const float*)d_in[2];
    const float* gw = (const float*)d_in[3];
    const float* gb = (const float*)d_in[4];
    float* out = (float*)d_out;

    __half *xA, *xB, *wh;
    cudaGetSymbolAddress((void**)&xA, g_xA);
    cudaGetSymbolAddress((void**)&xB, g_xB);
    cudaGetSymbolAddress((void**)&wh, g_w2);

    static int attr_done = 0;
    if (!attr_done) {
        cudaFuncSetAttribute(wavenet_mma_layer,
                             cudaFuncAttributeMaxDynamicSharedMemorySize, SM_TOTAL);
        attr_done = 1;
    }

    {
        const size_t gz = (size_t)2 * BATCH * 8 * GUARD * 32;
        zero_guards<<<(int)((gz + 255) / 256), 256>>>();
        const int total = NLAYERS * 2 * 16 * 256 * 32;
        prep_weights<<<(total + 255) / 256, 256>>>(fw, gw);
        dim3 tg(TLEN / 32, CHAN / 32, BATCH);
        prep_input<<<tg, dim3(32, 8)>>>(ys);
    }

    dim3 grid(TLEN / 128, CHAN / 64, BATCH);
    const __half* x = xA;
    __half* ybufs[2] = { xB, xA };
    for (int l = 0; l < NLAYERS; ++l) {
        __half* y = ybufs[l & 1];
        wavenet_mma_layer<<<grid, 256, SM_TOTAL>>>(
            x, wh + (size_t)l * 2 * 16 * 256 * 32,
            fb + l * CHAN, gb + l * CHAN,
            y, out, 1 << l, (l == 0) ? 1 : 0);
        x = y;
    }
}

// round 9
// speedup vs baseline: 4.9027x; 1.0867x over previous
#include <cuda_runtime.h>
#include <cuda_fp16.h>
#include <cstdint>
#include <math.h>

#define BATCH 16
#define CHAN  256
#define TLEN  4096
#define NLAYERS 8
#define NCHUNK 8                         // 8 chunks of k=64
#define GUARD 128
#define PROWS (GUARD + TLEN)             // 4224 rows per plane
#define PLANE ((size_t)PROWS * 64)       // halfs per (b,kc) plane (64-ch rows)
#define XBUF  ((size_t)BATCH * 4 * PLANE)

// ---------------- device scratch -------------------------------------------
// X planes: [b][kc4][GUARD+t][64ch], 8-quad swizzled, fp16, ping-pong
__device__ __align__(128) __half g_xA[XBUF];
__device__ __align__(128) __half g_xB[XBUF];
// W: [l][fg][chunk8][cout256][64k], 8-quad swizzled by cout
__device__ __align__(128) __half g_w2[(size_t)NLAYERS * 2 * 8 * 256 * 64];

// ---------------- smem geometry --------------------------------------------
// Stage: A 128x128B=16384 | Wf 64x128B=8192 | Wg 8192  = 32768
#define STAGE_BYTES 32768
#define STAGE_TX    32768
#define NSTAGE 3
#define MB_OFF (NSTAGE * STAGE_BYTES)       // 98304; full[3] then empty[3]
#define SM_TOTAL (MB_OFF + 64)

// ---------------- asm helpers ----------------------------------------------
__device__ __forceinline__ uint32_t smem_u32(const void* p) {
    uint32_t a;
    asm("{ .reg .u64 t; cvta.to.shared.u64 t, %1; cvt.u32.u64 %0, t; }" : "=r"(a) : "l"(p));
    return a;
}
#define MBARRIER_INIT(mbar, cnt) \
    asm volatile("mbarrier.init.shared.b64 [%0], %1;" :: "r"((uint32_t)(mbar)), "r"((uint32_t)(cnt)) : "memory")
#define MBARRIER_EXPECT_TX(mbar, tx) \
    asm volatile("mbarrier.arrive.expect_tx.shared.b64 _, [%0], %1;" :: "r"((uint32_t)(mbar)), "r"((uint32_t)(tx)) : "memory")
#define MBARRIER_ARRIVE(mbar) \
    asm volatile("mbarrier.arrive.shared.b64 _, [%0];" :: "r"((uint32_t)(mbar)) : "memory")
#define MBARRIER_WAIT_PARITY(mbar, par) do { \
    uint32_t _m = (uint32_t)(mbar); uint32_t _p = (uint32_t)(par); uint32_t _d; \
    asm volatile("{\n\t.reg .pred p;\n\tmbarrier.try_wait.parity.acquire.cta.shared::cta.b64 p, [%1], %2;\n\tselp.b32 %0,1,0,p;\n\t}" \
        : "=r"(_d) : "r"(_m), "r"(_p) : "memory"); \
    if (!_d) { \
        asm volatile("{\n\t.reg .pred P1;\n\tWL_%=:\n\tmbarrier.try_wait.parity.acquire.cta.shared::cta.b64 P1, [%0], %1, 0x989680;\n\t@P1 bra.uni WD_%=;\n\tbra.uni WL_%=;\n\tWD_%=:\n\t}" \
            :: "r"(_m), "r"(_p) : "memory"); \
    } } while (0)
__device__ __forceinline__ void bulk_ld(uint32_t dst, const void* src, uint32_t bytes, uint32_t mbar) {
    asm volatile("cp.async.bulk.shared::cluster.global.mbarrier::complete_tx::bytes [%0], [%1], %2, [%3];"
                 :: "r"(dst), "l"(src), "r"(bytes), "r"(mbar) : "memory");
}
__device__ __forceinline__ void ldsm4(uint32_t* r, uint32_t addr) {
    asm volatile("ldmatrix.sync.aligned.m8n8.x4.shared.b16 {%0,%1,%2,%3}, [%4];"
                 : "=r"(r[0]), "=r"(r[1]), "=r"(r[2]), "=r"(r[3]) : "r"(addr));
}
__device__ __forceinline__ void mma16816(float* d, const uint32_t* a, const uint32_t* b) {
    asm volatile("mma.sync.aligned.m16n8k16.row.col.f32.f16.f16.f32 "
                 "{%0,%1,%2,%3}, {%4,%5,%6,%7}, {%8,%9}, {%0,%1,%2,%3};"
                 : "+f"(d[0]), "+f"(d[1]), "+f"(d[2]), "+f"(d[3])
                 : "r"(a[0]), "r"(a[1]), "r"(a[2]), "r"(a[3]), "r"(b[0]), "r"(b[1]));
}

// ---------------- prep kernels ---------------------------------------------
__global__ void zero_guards() {
    const size_t per = (size_t)BATCH * 4 * GUARD * 64;    // 524288
    size_t i = (size_t)blockIdx.x * blockDim.x + threadIdx.x;
    if (i >= 2 * per) return;
    int arr = (int)(i / per);
    size_t r = i % per;
    size_t plane_i = r / (GUARD * 64);
    size_t within  = r % (GUARD * 64);
    __half* p = arr ? g_xB : g_xA;
    p[plane_i * PLANE + within] = __ushort_as_half(0);
}

// w[l][cout][cin][tap] -> g_w2[l][fg][chunk8][cout][64k], swizzle q^(cout&7)
__global__ void prep_weights(const float* __restrict__ fw, const float* __restrict__ gw) {
    int idx = blockIdx.x * blockDim.x + threadIdx.x;
    const int total = NLAYERS * 2 * 8 * 256 * 64;
    if (idx >= total) return;
    int kk   = idx & 63;
    int cout = (idx >> 6) & 255;
    int ch   = (idx >> 14) & 7;
    int fg   = (idx >> 17) & 1;
    int l    = idx >> 18;
    const float* w = fg ? gw : fw;
    int cin = (ch & 3) * 64 + kk;
    int tap = (ch < 4) ? 1 : 0;    // first 4 chunks = current sample
    float v = w[(((size_t)l * CHAN + cout) * CHAN + cin) * 2 + tap];
    int pos = (((kk >> 3) ^ (cout & 7)) << 3) | (kk & 7);
    g_w2[((((size_t)l * 2 + fg) * 8 + ch) * 256 + cout) * 64 + pos] = __float2half_rn(v);
}

// ys [b][c][t] f32 -> swizzled planes, fp16
__global__ void prep_input(const float* __restrict__ ys) {
    __shared__ float tile[32][33];
    const int b  = blockIdx.z;
    const int c0 = blockIdx.y * 32;
    const int t0 = blockIdx.x * 32;
    const int tx = threadIdx.x, ty = threadIdx.y;   // 32 x 8
#pragma unroll
    for (int i = 0; i < 32; i += 8)
        tile[ty + i][tx] = ys[((size_t)b * CHAN + c0 + ty + i) * TLEN + t0 + tx];
    __syncthreads();
    const int kc = c0 >> 6;
    const int qbase = (c0 & 32) >> 3;    // 0 or 4
#pragma unroll
    for (int i = 0; i < 32; i += 8) {
        int t = t0 + ty + i;
        int pos = (((qbase + (tx >> 3)) ^ (t & 7)) << 3) | (tx & 7);
        size_t o = (((size_t)b * 4 + kc) * PROWS + GUARD + t) * 64 + pos;
        g_xA[o] = __float2half_rn(tile[tx][ty + i]);
    }
}

// ---------------- fused HMMA layer kernel -----------------------------------
__global__ __launch_bounds__(256, 2)
void wavenet_mma_layer(const __half* __restrict__ X,
                       const __half* __restrict__ Wl,   // [fg][chunk8][256][64]
                       const float* __restrict__ fb,
                       const float* __restrict__ gb,
                       __half* __restrict__ Y,
                       float* __restrict__ Zout,
                       int dil, int first)
{
    extern __shared__ char smem[];
    const uint32_t sb = smem_u32(smem);
    const int tid  = threadIdx.x;
    const int wid  = tid >> 5;
    const int lane = tid & 31;
    const int t0    = blockIdx.x * 128;
    const int cout0 = blockIdx.y * 64;
    const int b     = blockIdx.z;

    const __half* Xb = X + (size_t)b * 4 * PLANE;

    const int m0 = (wid & 3) * 32;
    const int n0 = (wid >> 2) * 32;

    float accF[2][4][4], accG[2][4][4];
#pragma unroll
    for (int mi = 0; mi < 2; ++mi)
#pragma unroll
        for (int nt = 0; nt < 4; ++nt)
#pragma unroll
            for (int e = 0; e < 4; ++e) { accF[mi][nt][e] = 0.f; accG[mi][nt][e] = 0.f; }

    if (tid == 0) {
#pragma unroll
        for (int s = 0; s < NSTAGE; ++s) {
            MBARRIER_INIT(sb + MB_OFF + s * 8, 1);            // full: tx-based
            MBARRIER_INIT(sb + MB_OFF + 24 + s * 8, 8);       // empty: 8 warp arrivals
        }
    }
    __syncthreads();

#define ISSUE_CHUNK(C, S) do {                                                   \
        uint32_t _mb = sb + MB_OFF + (S) * 8;                                    \
        uint32_t _st = sb + (S) * STAGE_BYTES;                                   \
        int _sh = ((C) >= 4) ? dil : 0;                                          \
        int _kc = (C) & 3;                                                       \
        MBARRIER_EXPECT_TX(_mb, STAGE_TX);                                       \
        bulk_ld(_st,          Xb + ((size_t)_kc * PROWS + GUARD + t0 - _sh) * 64, 16384, _mb); \
        bulk_ld(_st + 16384,  Wl + ((size_t)(0 + (C)) * 256 + cout0) * 64, 8192, _mb); \
        bulk_ld(_st + 24576,  Wl + ((size_t)(8 + (C)) * 256 + cout0) * 64, 8192, _mb); \
    } while (0)

    if (tid == 0) {
        ISSUE_CHUNK(0, 0);
        ISSUE_CHUNK(1, 1);
        ISSUE_CHUNK(2, 2);
    }

    const int a_row = lane & 15;
    const uint32_t a_q0  = (uint32_t)(lane >> 4);          // 0/1
    const int b_row = ((lane >> 4) * 8) + (lane & 7);
    const uint32_t b_q0  = (uint32_t)((lane >> 3) & 1);    // 0/1
    const uint32_t bkey  = (uint32_t)(b_row & 7);

    int s = 0, f = 0;
    for (int c = 0; c < NCHUNK; ++c) {
        MBARRIER_WAIT_PARITY(sb + MB_OFF + s * 8, f & 1);

        const int shift = (c >= 4) ? dil : 0;
        const uint32_t sA = sb + s * STAGE_BYTES;
        const uint32_t sW = sA + 16384;
        const uint32_t akey = (uint32_t)((a_row - shift) & 7);

#pragma unroll
        for (int ks = 0; ks < 4; ++ks) {
            uint32_t a[2][4], bF[2][4], bG[2][4];
            const uint32_t qa = ((ks * 2 + a_q0) ^ akey) * 16;
            const uint32_t qb = ((ks * 2 + b_q0) ^ bkey) * 16;
#pragma unroll
            for (int mi = 0; mi < 2; ++mi)
                ldsm4(a[mi], sA + (m0 + mi * 16 + a_row) * 128 + qa);
#pragma unroll
            for (int nt2 = 0; nt2 < 2; ++nt2) {
                uint32_t adr = sW + (n0 + nt2 * 16 + b_row) * 128 + qb;
                ldsm4(bF[nt2], adr);
                ldsm4(bG[nt2], adr + 8192);
            }
#pragma unroll
            for (int mi = 0; mi < 2; ++mi)
#pragma unroll
                for (int nt2 = 0; nt2 < 2; ++nt2)
#pragma unroll
                    for (int sN = 0; sN < 2; ++sN) {
                        mma16816(accF[mi][nt2 * 2 + sN], a[mi], &bF[nt2][sN * 2]);
                        mma16816(accG[mi][nt2 * 2 + sN], a[mi], &bG[nt2][sN * 2]);
                    }
        }

        if (lane == 0) MBARRIER_ARRIVE(sb + MB_OFF + 24 + s * 8);
        if (tid == 0 && c + 3 < NCHUNK) {
            // stage s is reused by chunk c+3; wait until all 8 warps released it
            MBARRIER_WAIT_PARITY(sb + MB_OFF + 24 + s * 8, f & 1);
            ISSUE_CHUNK(c + 3, s);
        }
        if (++s == NSTAGE) { s = 0; ++f; }
    }
#undef ISSUE_CHUNK

    __syncthreads();   // all warps done before smem reuse as z tile

    // ---- epilogue: z tile [t][c] (stride 68), then coalesced writeout -------
    float* zs = reinterpret_cast<float*>(smem);   // 128 x 68 f32 = 34816 B
    {
        const int g  = lane >> 2;
        const int tg = lane & 3;
        float fbv[4][2], gbv[4][2];
#pragma unroll
        for (int nt = 0; nt < 4; ++nt)
#pragma unroll
            for (int p = 0; p < 2; ++p) {
                int cout = cout0 + n0 + nt * 8 + 2 * tg + p;
                fbv[nt][p] = __ldg(fb + cout);
                gbv[nt][p] = __ldg(gb + cout);
            }
#pragma unroll
        for (int mi = 0; mi < 2; ++mi)
#pragma unroll
            for (int nt = 0; nt < 4; ++nt)
#pragma unroll
                for (int e = 0; e < 4; ++e) {
                    int t_loc = m0 + mi * 16 + g + (e >> 1) * 8;
                    int c_loc = n0 + nt * 8 + 2 * tg + (e & 1);
                    float F = accF[mi][nt][e] + fbv[nt][e & 1];
                    float G = accG[mi][nt][e] + gbv[nt][e & 1];
                    float z = tanhf(F) * (0.5f * tanhf(0.5f * G) + 0.5f);
                    zs[t_loc * 68 + c_loc] = z;
                }
    }
    __syncthreads();

    // Y planes: cout block == one kc plane (64-ch rows), swizzled quad stores
    const int kc = cout0 >> 6;
#pragma unroll
    for (int i = 0; i < 4; ++i) {
        int id = tid + i * 256;
        int q8 = id & 7, t = id >> 3;
        const float* zr = zs + t * 68 + q8 * 8;
        float4 z0 = reinterpret_cast<const float4*>(zr)[0];
        float4 z1 = reinterpret_cast<const float4*>(zr)[1];
        float zv[8] = { z0.x, z0.y, z0.z, z0.w, z1.x, z1.y, z1.z, z1.w };
        uint32_t pk[4];
#pragma unroll
        for (int p = 0; p < 4; ++p) {
            __half h0 = __float2half_rn(zv[2 * p]);
            __half h1 = __float2half_rn(zv[2 * p + 1]);
            pk[p] = (uint32_t)__half_as_ushort(h0) | ((uint32_t)__half_as_ushort(h1) << 16);
        }
        int tgl = t0 + t;
        int swq = q8 ^ (tgl & 7);
        __half* dst = Y + (((size_t)b * 4 + kc) * PROWS + GUARD + tgl) * 64 + swq * 8;
        *reinterpret_cast<uint4*>(dst) = make_uint4(pk[0], pk[1], pk[2], pk[3]);
    }
    // Zout: [b][c][t] f32
    const size_t zb = (size_t)b * CHAN * TLEN;
#pragma unroll
    for (int i = 0; i < 32; ++i) {
        int id = tid + i * 256;
        int t = id & 127, cl = id >> 7;
        float z = zs[t * 68 + cl];
        size_t o = zb + (size_t)(cout0 + cl) * TLEN + t0 + t;
        if (first) Zout[o] = z;
        else       Zout[o] += z;
    }
}

// ---------------- launch ----------------------------------------------------
extern "C" void kernel_launch(void* const* d_in, const int* in_sizes, int n_in,
                              void* d_out, int out_size) {
    const float* ys = (const float*)d_in[0];
    const float* fw = (const float*)d_in[1];
    const float* fb = (const float*)d_in[2];
    const float* gw = (const float*)d_in[3];
    const float* gb = (const float*)d_in[4];
    float* out = (float*)d_out;

    __half *xA, *xB, *wh;
    cudaGetSymbolAddress((void**)&xA, g_xA);
    cudaGetSymbolAddress((void**)&xB, g_xB);
    cudaGetSymbolAddress((void**)&wh, g_w2);

    static int attr_done = 0;
    if (!attr_done) {
        cudaFuncSetAttribute(wavenet_mma_layer,
                             cudaFuncAttributeMaxDynamicSharedMemorySize, SM_TOTAL);
        attr_done = 1;
    }

    {
        const size_t gz = (size_t)2 * BATCH * 4 * GUARD * 64;
        zero_guards<<<(int)((gz + 255) / 256), 256>>>();
        const int total = NLAYERS * 2 * 8 * 256 * 64;
        prep_weights<<<(total + 255) / 256, 256>>>(fw, gw);
        dim3 tg(TLEN / 32, CHAN / 32, BATCH);
        prep_input<<<tg, dim3(32, 8)>>>(ys);
    }

    dim3 grid(TLEN / 128, CHAN / 64, BATCH);
    const __half* x = xA;
    __half* ybufs[2] = { xB, xA };
    for (int l = 0; l < NLAYERS; ++l) {
        __half* y = ybufs[l & 1];
        wavenet_mma_layer<<<grid, 256, SM_TOTAL>>>(
            x, wh + (size_t)l * 2 * 8 * 256 * 64,
            fb + l * CHAN, gb + l * CHAN,
            y, out, 1 << l, (l == 0) ? 1 : 0);
        x = y;
    }
}

// round 10
// speedup vs baseline: 4.9948x; 1.0188x over previous
#include <cuda_runtime.h>
#include <cuda_fp16.h>
#include <cstdint>
#include <math.h>

#define BATCH 16
#define CHAN  256
#define TLEN  4096
#define NLAYERS 8
#define NCHUNK 8                         // 8 chunks of k=64
#define GUARD 128
#define PROWS (GUARD + TLEN)             // 4224 rows per plane
#define PLANE ((size_t)PROWS * 64)       // halfs per (b,kc) plane (64-ch rows)
#define XBUF  ((size_t)BATCH * 4 * PLANE)

// ---------------- device scratch -------------------------------------------
// X planes: [b][kc4][GUARD+t][64ch], 8-quad swizzled, fp16, ping-pong
__device__ __align__(128) __half g_xA[XBUF];
__device__ __align__(128) __half g_xB[XBUF];
// W: [l][chunk8][coutblk4][fg2][64cout][64k], 8-quad swizzled by cout
__device__ __align__(128) __half g_w2[(size_t)NLAYERS * 8 * 4 * 2 * 64 * 64];

// ---------------- smem geometry --------------------------------------------
// Stage: A 128x128B=16384 | Wf 64x128B=8192 | Wg 8192  = 32768
#define STAGE_BYTES 32768
#define STAGE_TX    32768
#define NSTAGE 3
#define MB_OFF (NSTAGE * STAGE_BYTES)       // 98304; full[3] then empty[3]
#define SM_TOTAL (MB_OFF + 64)

// ---------------- asm helpers ----------------------------------------------
__device__ __forceinline__ uint32_t smem_u32(const void* p) {
    uint32_t a;
    asm("{ .reg .u64 t; cvta.to.shared.u64 t, %1; cvt.u32.u64 %0, t; }" : "=r"(a) : "l"(p));
    return a;
}
#define MBARRIER_INIT(mbar, cnt) \
    asm volatile("mbarrier.init.shared.b64 [%0], %1;" :: "r"((uint32_t)(mbar)), "r"((uint32_t)(cnt)) : "memory")
#define MBARRIER_EXPECT_TX(mbar, tx) \
    asm volatile("mbarrier.arrive.expect_tx.shared.b64 _, [%0], %1;" :: "r"((uint32_t)(mbar)), "r"((uint32_t)(tx)) : "memory")
#define MBARRIER_ARRIVE(mbar) \
    asm volatile("mbarrier.arrive.shared.b64 _, [%0];" :: "r"((uint32_t)(mbar)) : "memory")
#define MBARRIER_WAIT_PARITY(mbar, par) do { \
    uint32_t _m = (uint32_t)(mbar); uint32_t _p = (uint32_t)(par); uint32_t _d; \
    asm volatile("{\n\t.reg .pred p;\n\tmbarrier.try_wait.parity.acquire.cta.shared::cta.b64 p, [%1], %2;\n\tselp.b32 %0,1,0,p;\n\t}" \
        : "=r"(_d) : "r"(_m), "r"(_p) : "memory"); \
    if (!_d) { \
        asm volatile("{\n\t.reg .pred P1;\n\tWL_%=:\n\tmbarrier.try_wait.parity.acquire.cta.shared::cta.b64 P1, [%0], %1, 0x989680;\n\t@P1 bra.uni WD_%=;\n\tbra.uni WL_%=;\n\tWD_%=:\n\t}" \
            :: "r"(_m), "r"(_p) : "memory"); \
    } } while (0)
__device__ __forceinline__ void bulk_ld(uint32_t dst, const void* src, uint32_t bytes, uint32_t mbar) {
    asm volatile("cp.async.bulk.shared::cluster.global.mbarrier::complete_tx::bytes [%0], [%1], %2, [%3];"
                 :: "r"(dst), "l"(src), "r"(bytes), "r"(mbar) : "memory");
}
__device__ __forceinline__ void ldsm4(uint32_t* r, uint32_t addr) {
    asm volatile("ldmatrix.sync.aligned.m8n8.x4.shared.b16 {%0,%1,%2,%3}, [%4];"
                 : "=r"(r[0]), "=r"(r[1]), "=r"(r[2]), "=r"(r[3]) : "r"(addr));
}
__device__ __forceinline__ void mma16816(float* d, const uint32_t* a, const uint32_t* b) {
    asm volatile("mma.sync.aligned.m16n8k16.row.col.f32.f16.f16.f32 "
                 "{%0,%1,%2,%3}, {%4,%5,%6,%7}, {%8,%9}, {%0,%1,%2,%3};"
                 : "+f"(d[0]), "+f"(d[1]), "+f"(d[2]), "+f"(d[3])
                 : "r"(a[0]), "r"(a[1]), "r"(a[2]), "r"(a[3]), "r"(b[0]), "r"(b[1]));
}

// ---------------- prep kernels ---------------------------------------------
__global__ void zero_guards() {
    const size_t per = (size_t)BATCH * 4 * GUARD * 64;    // 524288
    size_t i = (size_t)blockIdx.x * blockDim.x + threadIdx.x;
    if (i >= 2 * per) return;
    int arr = (int)(i / per);
    size_t r = i % per;
    size_t plane_i = r / (GUARD * 64);
    size_t within  = r % (GUARD * 64);
    __half* p = arr ? g_xB : g_xA;
    p[plane_i * PLANE + within] = __ushort_as_half(0);
}

// w[l][cout][cin][tap] -> g_w2[l][ch][cb][fg][co][64k], swizzle q^(cout&7)
__global__ void prep_weights(const float* __restrict__ fw, const float* __restrict__ gw) {
    int idx = blockIdx.x * blockDim.x + threadIdx.x;
    const int total = NLAYERS * 2 * 8 * 256 * 64;
    if (idx >= total) return;
    int kk   = idx & 63;
    int cout = (idx >> 6) & 255;
    int ch   = (idx >> 14) & 7;
    int fg   = (idx >> 17) & 1;
    int l    = idx >> 18;
    const float* w = fg ? gw : fw;
    int cin = (ch & 3) * 64 + kk;
    int tap = (ch < 4) ? 1 : 0;    // first 4 chunks = current sample
    float v = w[(((size_t)l * CHAN + cout) * CHAN + cin) * 2 + tap];
    int pos = (((kk >> 3) ^ (cout & 7)) << 3) | (kk & 7);
    size_t o = (((((size_t)l * 8 + ch) * 4 + (cout >> 6)) * 2 + fg) * 64 + (cout & 63)) * 64 + pos;
    g_w2[o] = __float2half_rn(v);
}

// ys [b][c][t] f32 -> swizzled planes, fp16
__global__ void prep_input(const float* __restrict__ ys) {
    __shared__ float tile[32][33];
    const int b  = blockIdx.z;
    const int c0 = blockIdx.y * 32;
    const int t0 = blockIdx.x * 32;
    const int tx = threadIdx.x, ty = threadIdx.y;   // 32 x 8
#pragma unroll
    for (int i = 0; i < 32; i += 8)
        tile[ty + i][tx] = ys[((size_t)b * CHAN + c0 + ty + i) * TLEN + t0 + tx];
    __syncthreads();
    const int kc = c0 >> 6;
    const int qbase = (c0 & 32) >> 3;    // 0 or 4
#pragma unroll
    for (int i = 0; i < 32; i += 8) {
        int t = t0 + ty + i;
        int pos = (((qbase + (tx >> 3)) ^ (t & 7)) << 3) | (tx & 7);
        size_t o = (((size_t)b * 4 + kc) * PROWS + GUARD + t) * 64 + pos;
        g_xA[o] = __float2half_rn(tile[tx][ty + i]);
    }
}

// ---------------- fused HMMA layer kernel -----------------------------------
__global__ __launch_bounds__(256, 2)
void wavenet_mma_layer(const __half* __restrict__ X,
                       const __half* __restrict__ Wl,   // [ch8][cb4][fg2][64][64]
                       const float* __restrict__ fb,
                       const float* __restrict__ gb,
                       __half* __restrict__ Y,
                       float* __restrict__ Zout,
                       int dil, int first)
{
    extern __shared__ char smem[];
    const uint32_t sb = smem_u32(smem);
    const int tid  = threadIdx.x;
    const int wid  = tid >> 5;
    const int lane = tid & 31;
    const int t0    = blockIdx.x * 128;
    const int cout0 = blockIdx.y * 64;
    const int b     = blockIdx.z;

    const __half* Xb = X + (size_t)b * 4 * PLANE;

    const int m0 = (wid & 3) * 32;
    const int n0 = (wid >> 2) * 32;

    float accF[2][4][4], accG[2][4][4];
#pragma unroll
    for (int mi = 0; mi < 2; ++mi)
#pragma unroll
        for (int nt = 0; nt < 4; ++nt)
#pragma unroll
            for (int e = 0; e < 4; ++e) { accF[mi][nt][e] = 0.f; accG[mi][nt][e] = 0.f; }

    if (tid == 0) {
#pragma unroll
        for (int s = 0; s < NSTAGE; ++s) {
            MBARRIER_INIT(sb + MB_OFF + s * 8, 1);            // full: tx-based
            MBARRIER_INIT(sb + MB_OFF + 24 + s * 8, 8);       // empty: 8 warp arrivals
        }
    }
    __syncthreads();

#define ISSUE_CHUNK(C, S) do {                                                   \
        uint32_t _mb = sb + MB_OFF + (S) * 8;                                    \
        uint32_t _st = sb + (S) * STAGE_BYTES;                                   \
        int _sh = ((C) >= 4) ? dil : 0;                                          \
        int _kc = (C) & 3;                                                       \
        MBARRIER_EXPECT_TX(_mb, STAGE_TX);                                       \
        bulk_ld(_st,          Xb + ((size_t)_kc * PROWS + GUARD + t0 - _sh) * 64, 16384, _mb); \
        bulk_ld(_st + 16384,  Wl + ((size_t)(C) * 4 + (cout0 >> 6)) * 8192, 16384, _mb); \
    } while (0)

    if (tid == 0) {
        ISSUE_CHUNK(0, 0);
        ISSUE_CHUNK(1, 1);
        ISSUE_CHUNK(2, 2);
    }

    // ---- loop-invariant ldsm addressing ----
    const int a_row = lane & 15;
    const uint32_t a_q0  = (uint32_t)(lane >> 4);          // 0/1
    const int b_row = ((lane >> 4) * 8) + (lane & 7);
    const uint32_t b_q0  = (uint32_t)((lane >> 3) & 1);    // 0/1
    const uint32_t aoff0 = (uint32_t)((m0 + a_row) * 128);
    const uint32_t aoff1 = aoff0 + 16 * 128;
    const uint32_t boff0 = (uint32_t)((n0 + b_row) * 128);
    const uint32_t boff1 = boff0 + 16 * 128;
    uint32_t qb[4];
#pragma unroll
    for (int ks = 0; ks < 4; ++ks)
        qb[ks] = (((uint32_t)(ks * 2) + b_q0) ^ (uint32_t)(b_row & 7)) * 16;

    uint32_t aT[2][4], bFT[2][2][4], bGT[2][2][4];

#define LDB(BUF, KS) do {                                                        \
        ldsm4(bFT[BUF][0], sWF + boff0 + qb[KS]);                                \
        ldsm4(bFT[BUF][1], sWF + boff1 + qb[KS]);                                \
        ldsm4(bGT[BUF][0], sWG + boff0 + qb[KS]);                                \
        ldsm4(bGT[BUF][1], sWG + boff1 + qb[KS]);                                \
    } while (0)
#define LDA(KS) do {                                                             \
        ldsm4(aT[0], sA + aoff0 + qa[KS]);                                       \
        ldsm4(aT[1], sA + aoff1 + qa[KS]);                                       \
    } while (0)
#define MMAS(BUF) do {                                                           \
        _Pragma("unroll")                                                        \
        for (int mi = 0; mi < 2; ++mi)                                           \
            _Pragma("unroll")                                                    \
            for (int nt2 = 0; nt2 < 2; ++nt2)                                    \
                _Pragma("unroll")                                                \
                for (int sN = 0; sN < 2; ++sN) {                                 \
                    mma16816(accF[mi][nt2 * 2 + sN], aT[mi], &bFT[BUF][nt2][sN * 2]); \
                    mma16816(accG[mi][nt2 * 2 + sN], aT[mi], &bGT[BUF][nt2][sN * 2]); \
                }                                                                \
    } while (0)

    int s = 0, f = 0;
    for (int c = 0; c < NCHUNK; ++c) {
        MBARRIER_WAIT_PARITY(sb + MB_OFF + s * 8, f & 1);

        const int shift = (c >= 4) ? dil : 0;
        const uint32_t sA  = sb + s * STAGE_BYTES;
        const uint32_t sWF = sA + 16384;
        const uint32_t sWG = sA + 24576;
        const uint32_t akey = (uint32_t)((a_row - shift) & 7);
        uint32_t qa[4];
#pragma unroll
        for (int ks = 0; ks < 4; ++ks)
            qa[ks] = (((uint32_t)(ks * 2) + a_q0) ^ akey) * 16;

        // software-pipelined: B operands one k-step ahead, A just-in-time
        LDB(0, 0);
        LDA(0); LDB(1, 1); MMAS(0);
        LDA(1); LDB(0, 2); MMAS(1);
        LDA(2); LDB(1, 3); MMAS(0);
        LDA(3);            MMAS(1);

        if (lane == 0) MBARRIER_ARRIVE(sb + MB_OFF + 24 + s * 8);
        if (tid == 0 && c + 3 < NCHUNK) {
            // stage s is reused by chunk c+3; wait until all 8 warps released it
            MBARRIER_WAIT_PARITY(sb + MB_OFF + 24 + s * 8, f & 1);
            ISSUE_CHUNK(c + 3, s);
        }
        if (++s == NSTAGE) { s = 0; ++f; }
    }
#undef ISSUE_CHUNK
#undef LDB
#undef LDA
#undef MMAS

    __syncthreads();   // all warps done before smem reuse as z tile

    // ---- epilogue: z tile [t][c] (stride 68), then coalesced writeout -------
    float* zs = reinterpret_cast<float*>(smem);   // 128 x 68 f32 = 34816 B
    {
        const int g  = lane >> 2;
        const int tg = lane & 3;
        float fbv[4][2], gbv[4][2];
#pragma unroll
        for (int nt = 0; nt < 4; ++nt)
#pragma unroll
            for (int p = 0; p < 2; ++p) {
                int cout = cout0 + n0 + nt * 8 + 2 * tg + p;
                fbv[nt][p] = __ldg(fb + cout);
                gbv[nt][p] = __ldg(gb + cout);
            }
#pragma unroll
        for (int mi = 0; mi < 2; ++mi)
#pragma unroll
            for (int nt = 0; nt < 4; ++nt)
#pragma unroll
                for (int e = 0; e < 4; ++e) {
                    int t_loc = m0 + mi * 16 + g + (e >> 1) * 8;
                    int c_loc = n0 + nt * 8 + 2 * tg + (e & 1);
                    float F = accF[mi][nt][e] + fbv[nt][e & 1];
                    float G = accG[mi][nt][e] + gbv[nt][e & 1];
                    float z = tanhf(F) * (0.5f * tanhf(0.5f * G) + 0.5f);
                    zs[t_loc * 68 + c_loc] = z;
                }
    }
    __syncthreads();

    // Y planes: cout block == one kc plane (64-ch rows), swizzled quad stores
    const int kc = cout0 >> 6;
#pragma unroll
    for (int i = 0; i < 4; ++i) {
        int id = tid + i * 256;
        int q8 = id & 7, t = id >> 3;
        const float* zr = zs + t * 68 + q8 * 8;
        float4 z0 = reinterpret_cast<const float4*>(zr)[0];
        float4 z1 = reinterpret_cast<const float4*>(zr)[1];
        float zv[8] = { z0.x, z0.y, z0.z, z0.w, z1.x, z1.y, z1.z, z1.w };
        uint32_t pk[4];
#pragma unroll
        for (int p = 0; p < 4; ++p) {
            __half h0 = __float2half_rn(zv[2 * p]);
            __half h1 = __float2half_rn(zv[2 * p + 1]);
            pk[p] = (uint32_t)__half_as_ushort(h0) | ((uint32_t)__half_as_ushort(h1) << 16);
        }
        int tgl = t0 + t;
        int swq = q8 ^ (tgl & 7);
        __half* dst = Y + (((size_t)b * 4 + kc) * PROWS + GUARD + tgl) * 64 + swq * 8;
        *reinterpret_cast<uint4*>(dst) = make_uint4(pk[0], pk[1], pk[2], pk[3]);
    }
    // Zout: [b][c][t] f32
    const size_t zb = (size_t)b * CHAN * TLEN;
#pragma unroll
    for (int i = 0; i < 32; ++i) {
        int id = tid + i * 256;
        int t = id & 127, cl = id >> 7;
        float z = zs[t * 68 + cl];
        size_t o = zb + (size_t)(cout0 + cl) * TLEN + t0 + t;
        if (first) Zout[o] = z;
        else       Zout[o] += z;
    }
}

// ---------------- launch ----------------------------------------------------
extern "C" void kernel_launch(void* const* d_in, const int* in_sizes, int n_in,
                              void* d_out, int out_size) {
    const float* ys = (const float*)d_in[0];
    const float* fw = (const float*)d_in[1];
    const float* fb = (const float*)d_in[2];
    const float* gw = (const float*)d_in[3];
    const float* gb = (const float*)d_in[4];
    float* out = (float*)d_out;

    __half *xA, *xB, *wh;
    cudaGetSymbolAddress((void**)&xA, g_xA);
    cudaGetSymbolAddress((void**)&xB, g_xB);
    cudaGetSymbolAddress((void**)&wh, g_w2);

    static int attr_done = 0;
    if (!attr_done) {
        cudaFuncSetAttribute(wavenet_mma_layer,
                             cudaFuncAttributeMaxDynamicSharedMemorySize, SM_TOTAL);
        attr_done = 1;
    }

    {
        const size_t gz = (size_t)2 * BATCH * 4 * GUARD * 64;
        zero_guards<<<(int)((gz + 255) / 256), 256>>>();
        const int total = NLAYERS * 2 * 8 * 256 * 64;
        prep_weights<<<(total + 255) / 256, 256>>>(fw, gw);
        dim3 tg(TLEN / 32, CHAN / 32, BATCH);
        prep_input<<<tg, dim3(32, 8)>>>(ys);
    }

    dim3 grid(TLEN / 128, CHAN / 64, BATCH);
    const __half* x = xA;
    __half* ybufs[2] = { xB, xA };
    for (int l = 0; l < NLAYERS; ++l) {
        __half* y = ybufs[l & 1];
        wavenet_mma_layer<<<grid, 256, SM_TOTAL>>>(
            x, wh + (size_t)l * 8 * 4 * 2 * 64 * 64,
            fb + l * CHAN, gb + l * CHAN,
            y, out, 1 << l, (l == 0) ? 1 : 0);
        x = y;
    }
}

// round 11
// speedup vs baseline: 5.9615x; 1.1935x over previous
#include <cuda_runtime.h>
#include <cuda_fp16.h>
#include <cstdint>
#include <math.h>

#define BATCH 16
#define CHAN  256
#define TLEN  4096
#define NLAYERS 8
#define NCHUNK 8                         // 8 chunks of k=64
#define GUARD 128
#define PROWS (GUARD + TLEN)             // 4224 rows per plane
#define PLANE ((size_t)PROWS * 64)       // halfs per (b,kc) plane (64-ch rows)
#define XBUF  ((size_t)BATCH * 4 * PLANE)

// ---------------- device scratch -------------------------------------------
// X planes: [b][kc4][GUARD+t][64ch], 8-quad swizzled, fp16, ping-pong
__device__ __align__(128) __half g_xA[XBUF];
__device__ __align__(128) __half g_xB[XBUF];
// W: [l][chunk8][cb8][fg2][32cout][64k], 8-quad swizzled by cout
__device__ __align__(128) __half g_w2[(size_t)NLAYERS * 8 * 8 * 2 * 32 * 64];

// ---------------- smem geometry --------------------------------------------
// Stage: A 128x128B=16384 | W (fg2 x 32 x 128B)=8192  = 24576
#define STAGE_BYTES 24576
#define STAGE_TX    24576
#define NSTAGE 3
#define MB_OFF (NSTAGE * STAGE_BYTES)       // 73728; full[3] then empty[3]
#define SM_TOTAL (MB_OFF + 64)              // 73792

// ---------------- asm helpers ----------------------------------------------
__device__ __forceinline__ uint32_t smem_u32(const void* p) {
    uint32_t a;
    asm("{ .reg .u64 t; cvta.to.shared.u64 t, %1; cvt.u32.u64 %0, t; }" : "=r"(a) : "l"(p));
    return a;
}
#define MBARRIER_INIT(mbar, cnt) \
    asm volatile("mbarrier.init.shared.b64 [%0], %1;" :: "r"((uint32_t)(mbar)), "r"((uint32_t)(cnt)) : "memory")
#define MBARRIER_EXPECT_TX(mbar, tx) \
    asm volatile("mbarrier.arrive.expect_tx.shared.b64 _, [%0], %1;" :: "r"((uint32_t)(mbar)), "r"((uint32_t)(tx)) : "memory")
#define MBARRIER_ARRIVE(mbar) \
    asm volatile("mbarrier.arrive.shared.b64 _, [%0];" :: "r"((uint32_t)(mbar)) : "memory")
#define MBARRIER_WAIT_PARITY(mbar, par) do { \
    uint32_t _m = (uint32_t)(mbar); uint32_t _p = (uint32_t)(par); uint32_t _d; \
    asm volatile("{\n\t.reg .pred p;\n\tmbarrier.try_wait.parity.acquire.cta.shared::cta.b64 p, [%1], %2;\n\tselp.b32 %0,1,0,p;\n\t}" \
        : "=r"(_d) : "r"(_m), "r"(_p) : "memory"); \
    if (!_d) { \
        asm volatile("{\n\t.reg .pred P1;\n\tWL_%=:\n\tmbarrier.try_wait.parity.acquire.cta.shared::cta.b64 P1, [%0], %1, 0x989680;\n\t@P1 bra.uni WD_%=;\n\tbra.uni WL_%=;\n\tWD_%=:\n\t}" \
            :: "r"(_m), "r"(_p) : "memory"); \
    } } while (0)
__device__ __forceinline__ void bulk_ld(uint32_t dst, const void* src, uint32_t bytes, uint32_t mbar) {
    asm volatile("cp.async.bulk.shared::cluster.global.mbarrier::complete_tx::bytes [%0], [%1], %2, [%3];"
                 :: "r"(dst), "l"(src), "r"(bytes), "r"(mbar) : "memory");
}
__device__ __forceinline__ void ldsm4(uint32_t* r, uint32_t addr) {
    asm volatile("ldmatrix.sync.aligned.m8n8.x4.shared.b16 {%0,%1,%2,%3}, [%4];"
                 : "=r"(r[0]), "=r"(r[1]), "=r"(r[2]), "=r"(r[3]) : "r"(addr));
}
__device__ __forceinline__ void mma16816(float* d, const uint32_t* a, const uint32_t* b) {
    asm volatile("mma.sync.aligned.m16n8k16.row.col.f32.f16.f16.f32 "
                 "{%0,%1,%2,%3}, {%4,%5,%6,%7}, {%8,%9}, {%0,%1,%2,%3};"
                 : "+f"(d[0]), "+f"(d[1]), "+f"(d[2]), "+f"(d[3])
                 : "r"(a[0]), "r"(a[1]), "r"(a[2]), "r"(a[3]), "r"(b[0]), "r"(b[1]));
}

// ---------------- prep kernels ---------------------------------------------
__global__ void zero_guards() {
    const size_t per = (size_t)BATCH * 4 * GUARD * 64;    // 524288
    size_t i = (size_t)blockIdx.x * blockDim.x + threadIdx.x;
    if (i >= 2 * per) return;
    int arr = (int)(i / per);
    size_t r = i % per;
    size_t plane_i = r / (GUARD * 64);
    size_t within  = r % (GUARD * 64);
    __half* p = arr ? g_xB : g_xA;
    p[plane_i * PLANE + within] = __ushort_as_half(0);
}

// w[l][cout][cin][tap] -> g_w2[l][ch][cb][fg][co32][64k], swizzle q^(cout&7)
__global__ void prep_weights(const float* __restrict__ fw, const float* __restrict__ gw) {
    int idx = blockIdx.x * blockDim.x + threadIdx.x;
    const int total = NLAYERS * 2 * 8 * 256 * 64;
    if (idx >= total) return;
    int kk   = idx & 63;
    int cout = (idx >> 6) & 255;
    int ch   = (idx >> 14) & 7;
    int fg   = (idx >> 17) & 1;
    int l    = idx >> 18;
    const float* w = fg ? gw : fw;
    int cin = (ch & 3) * 64 + kk;
    int tap = (ch < 4) ? 1 : 0;    // first 4 chunks = current sample
    float v = w[(((size_t)l * CHAN + cout) * CHAN + cin) * 2 + tap];
    int pos = (((kk >> 3) ^ (cout & 7)) << 3) | (kk & 7);
    size_t o = (((((size_t)l * 8 + ch) * 8 + (cout >> 5)) * 2 + fg) * 32 + (cout & 31)) * 64 + pos;
    g_w2[o] = __float2half_rn(v);
}

// ys [b][c][t] f32 -> swizzled planes, fp16
__global__ void prep_input(const float* __restrict__ ys) {
    __shared__ float tile[32][33];
    const int b  = blockIdx.z;
    const int c0 = blockIdx.y * 32;
    const int t0 = blockIdx.x * 32;
    const int tx = threadIdx.x, ty = threadIdx.y;   // 32 x 8
#pragma unroll
    for (int i = 0; i < 32; i += 8)
        tile[ty + i][tx] = ys[((size_t)b * CHAN + c0 + ty + i) * TLEN + t0 + tx];
    __syncthreads();
    const int kc = c0 >> 6;
    const int qbase = (c0 & 32) >> 3;    // 0 or 4
#pragma unroll
    for (int i = 0; i < 32; i += 8) {
        int t = t0 + ty + i;
        int pos = (((qbase + (tx >> 3)) ^ (t & 7)) << 3) | (tx & 7);
        size_t o = (((size_t)b * 4 + kc) * PROWS + GUARD + t) * 64 + pos;
        g_xA[o] = __float2half_rn(tile[tx][ty + i]);
    }
}

// ---------------- fused HMMA layer kernel (128t x 32cout tile) ---------------
__global__ __launch_bounds__(256, 3)
void wavenet_mma_layer(const __half* __restrict__ X,
                       const __half* __restrict__ Wl,   // [ch8][cb8][fg2][32][64]
                       const float* __restrict__ fb,
                       const float* __restrict__ gb,
                       __half* __restrict__ Y,
                       float* __restrict__ Zout,
                       int dil, int first)
{
    extern __shared__ char smem[];
    const uint32_t sb = smem_u32(smem);
    const int tid  = threadIdx.x;
    const int wid  = tid >> 5;
    const int lane = tid & 31;
    const int t0    = blockIdx.x * 128;
    const int cout0 = blockIdx.y * 32;
    const int b     = blockIdx.z;
    const int cb    = cout0 >> 5;

    const __half* Xb = X + (size_t)b * 4 * PLANE;

    const int m0 = (wid & 3) * 32;       // t within tile
    const int n0 = (wid >> 2) * 16;      // cout within tile (0 or 16)

    float accF[2][2][4], accG[2][2][4];
#pragma unroll
    for (int mi = 0; mi < 2; ++mi)
#pragma unroll
        for (int sN = 0; sN < 2; ++sN)
#pragma unroll
            for (int e = 0; e < 4; ++e) { accF[mi][sN][e] = 0.f; accG[mi][sN][e] = 0.f; }

    if (tid == 0) {
#pragma unroll
        for (int s = 0; s < NSTAGE; ++s) {
            MBARRIER_INIT(sb + MB_OFF + s * 8, 1);            // full: tx-based
            MBARRIER_INIT(sb + MB_OFF + 24 + s * 8, 8);       // empty: 8 warp arrivals
        }
    }
    __syncthreads();

#define ISSUE_CHUNK(C, S) do {                                                   \
        uint32_t _mb = sb + MB_OFF + (S) * 8;                                    \
        uint32_t _st = sb + (S) * STAGE_BYTES;                                   \
        int _sh = ((C) >= 4) ? dil : 0;                                          \
        int _kc = (C) & 3;                                                       \
        MBARRIER_EXPECT_TX(_mb, STAGE_TX);                                       \
        bulk_ld(_st,          Xb + ((size_t)_kc * PROWS + GUARD + t0 - _sh) * 64, 16384, _mb); \
        bulk_ld(_st + 16384,  Wl + ((size_t)(C) * 8 + cb) * 4096, 8192, _mb);    \
    } while (0)

    if (tid == 0) {
        ISSUE_CHUNK(0, 0);
        ISSUE_CHUNK(1, 1);
        ISSUE_CHUNK(2, 2);
    }

    // ---- loop-invariant ldsm addressing ----
    const int a_row = lane & 15;
    const uint32_t a_q0  = (uint32_t)(lane >> 4);          // 0/1
    const int b_row = ((lane >> 4) * 8) + (lane & 7);      // 0..15
    const uint32_t b_q0  = (uint32_t)((lane >> 3) & 1);    // 0/1
    const uint32_t aoff0 = (uint32_t)((m0 + a_row) * 128);
    const uint32_t aoff1 = aoff0 + 16 * 128;
    const uint32_t boff  = (uint32_t)((n0 + b_row) * 128);
    uint32_t qb[4];
#pragma unroll
    for (int ks = 0; ks < 4; ++ks)
        qb[ks] = (((uint32_t)(ks * 2) + b_q0) ^ (uint32_t)(b_row & 7)) * 16;

    int s = 0, f = 0;
    for (int c = 0; c < NCHUNK; ++c) {
        MBARRIER_WAIT_PARITY(sb + MB_OFF + s * 8, f & 1);

        const int shift = (c >= 4) ? dil : 0;
        const uint32_t sA  = sb + s * STAGE_BYTES;
        const uint32_t sWF = sA + 16384;
        const uint32_t sWG = sA + 20480;
        const uint32_t akey = (uint32_t)((a_row - shift) & 7);

#pragma unroll
        for (int ks = 0; ks < 4; ++ks) {
            const uint32_t qa = (((uint32_t)(ks * 2) + a_q0) ^ akey) * 16;
            uint32_t aT[2][4], bF[4], bG[4];
            ldsm4(aT[0], sA + aoff0 + qa);
            ldsm4(aT[1], sA + aoff1 + qa);
            ldsm4(bF, sWF + boff + qb[ks]);
            ldsm4(bG, sWG + boff + qb[ks]);
#pragma unroll
            for (int mi = 0; mi < 2; ++mi)
#pragma unroll
                for (int sN = 0; sN < 2; ++sN) {
                    mma16816(accF[mi][sN], aT[mi], &bF[sN * 2]);
                    mma16816(accG[mi][sN], aT[mi], &bG[sN * 2]);
                }
        }

        if (lane == 0) {
            MBARRIER_ARRIVE(sb + MB_OFF + 24 + s * 8);
            if (wid == (c & 7) && c + 3 < NCHUNK) {
                // stage s reused by chunk c+3; rotating producer absorbs the wait
                MBARRIER_WAIT_PARITY(sb + MB_OFF + 24 + s * 8, f & 1);
                ISSUE_CHUNK(c + 3, s);
            }
        }
        if (++s == NSTAGE) { s = 0; ++f; }
    }
#undef ISSUE_CHUNK

    __syncthreads();   // all warps done before smem reuse as z tile

    // ---- epilogue: z tile [t][c] (stride 36), then coalesced writeout -------
    float* zs = reinterpret_cast<float*>(smem);   // 128 x 36 f32 = 18432 B
    {
        const int g  = lane >> 2;
        const int tg = lane & 3;
        float fbv[2][2], gbv[2][2];
#pragma unroll
        for (int sN = 0; sN < 2; ++sN)
#pragma unroll
            for (int p = 0; p < 2; ++p) {
                int cout = cout0 + n0 + sN * 8 + 2 * tg + p;
                fbv[sN][p] = __ldg(fb + cout);
                gbv[sN][p] = __ldg(gb + cout);
            }
#pragma unroll
        for (int mi = 0; mi < 2; ++mi)
#pragma unroll
            for (int sN = 0; sN < 2; ++sN)
#pragma unroll
                for (int e = 0; e < 4; ++e) {
                    int t_loc = m0 + mi * 16 + g + (e >> 1) * 8;
                    int c_loc = n0 + sN * 8 + 2 * tg + (e & 1);
                    float F = accF[mi][sN][e] + fbv[sN][e & 1];
                    float G = accG[mi][sN][e] + gbv[sN][e & 1];
                    float z = tanhf(F) * (0.5f * tanhf(0.5f * G) + 0.5f);
                    zs[t_loc * 36 + c_loc] = z;
                }
    }
    __syncthreads();

    // Y planes: 32-cout half-row, swizzled quad stores (2 iters of uint4)
    const int kc = cout0 >> 6;
    const int qb0 = (cout0 & 32) >> 3;   // 0 or 4
#pragma unroll
    for (int i = 0; i < 2; ++i) {
        int id = tid + i * 256;          // 512 total
        int q8 = id & 3, t = id >> 2;
        const float* zr = zs + t * 36 + q8 * 8;
        float4 z0 = reinterpret_cast<const float4*>(zr)[0];
        float4 z1 = reinterpret_cast<const float4*>(zr)[1];
        float zv[8] = { z0.x, z0.y, z0.z, z0.w, z1.x, z1.y, z1.z, z1.w };
        uint32_t pk[4];
#pragma unroll
        for (int p = 0; p < 4; ++p) {
            __half h0 = __float2half_rn(zv[2 * p]);
            __half h1 = __float2half_rn(zv[2 * p + 1]);
            pk[p] = (uint32_t)__half_as_ushort(h0) | ((uint32_t)__half_as_ushort(h1) << 16);
        }
        int tgl = t0 + t;
        int swq = (qb0 + q8) ^ (tgl & 7);
        __half* dst = Y + (((size_t)b * 4 + kc) * PROWS + GUARD + tgl) * 64 + swq * 8;
        *reinterpret_cast<uint4*>(dst) = make_uint4(pk[0], pk[1], pk[2], pk[3]);
    }
    // Zout: [b][c][t] f32
    const size_t zb = (size_t)b * CHAN * TLEN;
#pragma unroll
    for (int i = 0; i < 16; ++i) {
        int id = tid + i * 256;          // 4096 total
        int t = id & 127, cl = id >> 7;  // cl 0..31
        float z = zs[t * 36 + cl];
        size_t o = zb + (size_t)(cout0 + cl) * TLEN + t0 + t;
        if (first) Zout[o] = z;
        else       Zout[o] += z;
    }
}

// ---------------- launch ----------------------------------------------------
extern "C" void kernel_launch(void* const* d_in, const int* in_sizes, int n_in,
                              void* d_out, int out_size) {
    const float* ys = (const float*)d_in[0];
    const float* fw = (const float*)d_in[1];
    const float* fb = (const float*)d_in[2];
    const float* gw = (const float*)d_in[3];
    const float* gb = (const float*)d_in[4];
    float* out = (float*)d_out;

    __half *xA, *xB, *wh;
    cudaGetSymbolAddress((void**)&xA, g_xA);
    cudaGetSymbolAddress((void**)&xB, g_xB);
    cudaGetSymbolAddress((void**)&wh, g_w2);

    static int attr_done = 0;
    if (!attr_done) {
        cudaFuncSetAttribute(wavenet_mma_layer,
                             cudaFuncAttributeMaxDynamicSharedMemorySize, SM_TOTAL);
        attr_done = 1;
    }

    {
        const size_t gz = (size_t)2 * BATCH * 4 * GUARD * 64;
        zero_guards<<<(int)((gz + 255) / 256), 256>>>();
        const int total = NLAYERS * 2 * 8 * 256 * 64;
        prep_weights<<<(total + 255) / 256, 256>>>(fw, gw);
        dim3 tg(TLEN / 32, CHAN / 32, BATCH);
        prep_input<<<tg, dim3(32, 8)>>>(ys);
    }

    dim3 grid(TLEN / 128, CHAN / 32, BATCH);
    const __half* x = xA;
    __half* ybufs[2] = { xB, xA };
    for (int l = 0; l < NLAYERS; ++l) {
        __half* y = ybufs[l & 1];
        wavenet_mma_layer<<<grid, 256, SM_TOTAL>>>(
            x, wh + (size_t)l * 8 * 8 * 2 * 32 * 64,
            fb + l * CHAN, gb + l * CHAN,
            y, out, 1 << l, (l == 0) ? 1 : 0);
        x = y;
    }
}

// round 12
// speedup vs baseline: 6.0044x; 1.0072x over previous
#include <cuda_runtime.h>
#include <cuda_fp16.h>
#include <cstdint>
#include <math.h>

#define BATCH 16
#define CHAN  256
#define TLEN  4096
#define NLAYERS 8
#define NCHUNK 8                         // 8 chunks of k=64
#define GUARD 128
#define PROWS (GUARD + TLEN)             // 4224 rows per plane
#define PLANE ((size_t)PROWS * 64)       // halfs per (b,kc) plane (64-ch rows)
#define XBUF  ((size_t)BATCH * 4 * PLANE)
#define NTILES 4096                      // 32 t-tiles x 8 cout-blocks x 16 batch

// ---------------- device scratch -------------------------------------------
__device__ __align__(128) __half g_xA[XBUF];
__device__ __align__(128) __half g_xB[XBUF];
// W: [l][chunk8][cb8][fg2][32cout][64k], 8-quad swizzled by cout
__device__ __align__(128) __half g_w2[(size_t)NLAYERS * 8 * 8 * 2 * 32 * 64];
// persistent-kernel sync state (re-zeroed each launch)
__device__ int g_counter[NLAYERS];
__device__ int g_arrive[NLAYERS];

// ---------------- smem geometry --------------------------------------------
#define STAGE_BYTES 24576
#define STAGE_TX    24576
#define NSTAGE 3
#define MB_OFF (NSTAGE * STAGE_BYTES)       // 73728; full[3] then empty[3]
#define SM_TOTAL (MB_OFF + 64)              // 73792 dynamic

// ---------------- asm helpers ----------------------------------------------
__device__ __forceinline__ uint32_t smem_u32(const void* p) {
    uint32_t a;
    asm("{ .reg .u64 t; cvta.to.shared.u64 t, %1; cvt.u32.u64 %0, t; }" : "=r"(a) : "l"(p));
    return a;
}
#define MBARRIER_INIT(mbar, cnt) \
    asm volatile("mbarrier.init.shared.b64 [%0], %1;" :: "r"((uint32_t)(mbar)), "r"((uint32_t)(cnt)) : "memory")
#define MBARRIER_EXPECT_TX(mbar, tx) \
    asm volatile("mbarrier.arrive.expect_tx.shared.b64 _, [%0], %1;" :: "r"((uint32_t)(mbar)), "r"((uint32_t)(tx)) : "memory")
#define MBARRIER_ARRIVE(mbar) \
    asm volatile("mbarrier.arrive.shared.b64 _, [%0];" :: "r"((uint32_t)(mbar)) : "memory")
#define MBARRIER_WAIT_PARITY(mbar, par) do { \
    uint32_t _m = (uint32_t)(mbar); uint32_t _p = (uint32_t)(par); uint32_t _d; \
    asm volatile("{\n\t.reg .pred p;\n\tmbarrier.try_wait.parity.acquire.cta.shared::cta.b64 p, [%1], %2;\n\tselp.b32 %0,1,0,p;\n\t}" \
        : "=r"(_d) : "r"(_m), "r"(_p) : "memory"); \
    if (!_d) { \
        asm volatile("{\n\t.reg .pred P1;\n\tWL_%=:\n\tmbarrier.try_wait.parity.acquire.cta.shared::cta.b64 P1, [%0], %1, 0x989680;\n\t@P1 bra.uni WD_%=;\n\tbra.uni WL_%=;\n\tWD_%=:\n\t}" \
            :: "r"(_m), "r"(_p) : "memory"); \
    } } while (0)
__device__ __forceinline__ void bulk_ld(uint32_t dst, const void* src, uint32_t bytes, uint32_t mbar) {
    asm volatile("cp.async.bulk.shared::cluster.global.mbarrier::complete_tx::bytes [%0], [%1], %2, [%3];"
                 :: "r"(dst), "l"(src), "r"(bytes), "r"(mbar) : "memory");
}
__device__ __forceinline__ void ldsm4(uint32_t* r, uint32_t addr) {
    asm volatile("ldmatrix.sync.aligned.m8n8.x4.shared.b16 {%0,%1,%2,%3}, [%4];"
                 : "=r"(r[0]), "=r"(r[1]), "=r"(r[2]), "=r"(r[3]) : "r"(addr));
}
__device__ __forceinline__ void mma16816(float* d, const uint32_t* a, const uint32_t* b) {
    asm volatile("mma.sync.aligned.m16n8k16.row.col.f32.f16.f16.f32 "
                 "{%0,%1,%2,%3}, {%4,%5,%6,%7}, {%8,%9}, {%0,%1,%2,%3};"
                 : "+f"(d[0]), "+f"(d[1]), "+f"(d[2]), "+f"(d[3])
                 : "r"(a[0]), "r"(a[1]), "r"(a[2]), "r"(a[3]), "r"(b[0]), "r"(b[1]));
}

// ---------------- prep kernels ---------------------------------------------
__global__ void init_sync() {
    if (threadIdx.x < NLAYERS) {
        g_counter[threadIdx.x] = 0;
        g_arrive[threadIdx.x] = 0;
    }
}

__global__ void zero_guards() {
    const size_t per = (size_t)BATCH * 4 * GUARD * 64;    // 524288
    size_t i = (size_t)blockIdx.x * blockDim.x + threadIdx.x;
    if (i >= 2 * per) return;
    int arr = (int)(i / per);
    size_t r = i % per;
    size_t plane_i = r / (GUARD * 64);
    size_t within  = r % (GUARD * 64);
    __half* p = arr ? g_xB : g_xA;
    p[plane_i * PLANE + within] = __ushort_as_half(0);
}

// w[l][cout][cin][tap] -> g_w2[l][ch][cb][fg][co32][64k], swizzle q^(cout&7)
__global__ void prep_weights(const float* __restrict__ fw, const float* __restrict__ gw) {
    int idx = blockIdx.x * blockDim.x + threadIdx.x;
    const int total = NLAYERS * 2 * 8 * 256 * 64;
    if (idx >= total) return;
    int kk   = idx & 63;
    int cout = (idx >> 6) & 255;
    int ch   = (idx >> 14) & 7;
    int fg   = (idx >> 17) & 1;
    int l    = idx >> 18;
    const float* w = fg ? gw : fw;
    int cin = (ch & 3) * 64 + kk;
    int tap = (ch < 4) ? 1 : 0;    // first 4 chunks = current sample
    float v = w[(((size_t)l * CHAN + cout) * CHAN + cin) * 2 + tap];
    int pos = (((kk >> 3) ^ (cout & 7)) << 3) | (kk & 7);
    size_t o = (((((size_t)l * 8 + ch) * 8 + (cout >> 5)) * 2 + fg) * 32 + (cout & 31)) * 64 + pos;
    g_w2[o] = __float2half_rn(v);
}

// ys [b][c][t] f32 -> swizzled planes, fp16
__global__ void prep_input(const float* __restrict__ ys) {
    __shared__ float tile[32][33];
    const int b  = blockIdx.z;
    const int c0 = blockIdx.y * 32;
    const int t0 = blockIdx.x * 32;
    const int tx = threadIdx.x, ty = threadIdx.y;   // 32 x 8
#pragma unroll
    for (int i = 0; i < 32; i += 8)
        tile[ty + i][tx] = ys[((size_t)b * CHAN + c0 + ty + i) * TLEN + t0 + tx];
    __syncthreads();
    const int kc = c0 >> 6;
    const int qbase = (c0 & 32) >> 3;    // 0 or 4
#pragma unroll
    for (int i = 0; i < 32; i += 8) {
        int t = t0 + ty + i;
        int pos = (((qbase + (tx >> 3)) ^ (t & 7)) << 3) | (tx & 7);
        size_t o = (((size_t)b * 4 + kc) * PROWS + GUARD + t) * 64 + pos;
        g_xA[o] = __float2half_rn(tile[tx][ty + i]);
    }
}

// ---------------- persistent fused 8-layer kernel ----------------------------
__global__ __launch_bounds__(256, 3)
void wavenet_persistent(__half* __restrict__ xAp, __half* __restrict__ xBp,
                        const __half* __restrict__ Wbase,
                        const float* __restrict__ fbase,
                        const float* __restrict__ gbase,
                        float* __restrict__ Zout, int nCTA)
{
    extern __shared__ char smem[];
    __shared__ int s_tile;
    const uint32_t sb = smem_u32(smem);
    const int tid  = threadIdx.x;
    const int wid  = tid >> 5;
    const int lane = tid & 31;

    if (tid == 0) {
#pragma unroll
        for (int s = 0; s < NSTAGE; ++s) {
            MBARRIER_INIT(sb + MB_OFF + s * 8, 1);            // full: tx-based
            MBARRIER_INIT(sb + MB_OFF + 24 + s * 8, 8);       // empty: 8 warp arrivals
        }
    }
    __syncthreads();

    // ---- loop-invariant ldsm addressing ----
    const int m0 = (wid & 3) * 32;       // t within tile
    const int n0 = (wid >> 2) * 16;      // cout within tile (0 or 16)
    const int a_row = lane & 15;
    const uint32_t a_q0  = (uint32_t)(lane >> 4);
    const int b_row = ((lane >> 4) * 8) + (lane & 7);
    const uint32_t b_q0  = (uint32_t)((lane >> 3) & 1);
    const uint32_t aoff0 = (uint32_t)((m0 + a_row) * 128);
    const uint32_t aoff1 = aoff0 + 16 * 128;
    const uint32_t boff  = (uint32_t)((n0 + b_row) * 128);
    uint32_t qbv[4];
#pragma unroll
    for (int ks = 0; ks < 4; ++ks)
        qbv[ks] = (((uint32_t)(ks * 2) + b_q0) ^ (uint32_t)(b_row & 7)) * 16;

    // rolling pipeline state (continuous across tiles and layers)
    int sC = 0, fC = 0;        // consume: stage, phase
    int sI = 0, fI = 0;        // issue:   stage, phase
    int issued = 0;

    for (int l = 0; l < NLAYERS; ++l) {
        const __half* X = (l & 1) ? xBp : xAp;
        __half*       Y = (l & 1) ? xAp : xBp;
        const __half* Wl = Wbase + (size_t)l * 8 * 8 * 2 * 32 * 64;
        const float*  fb = fbase + l * CHAN;
        const float*  gb = gbase + l * CHAN;
        const int dil   = 1 << l;
        const int first = (l == 0);

        while (true) {
            if (tid == 0) s_tile = atomicAdd(&g_counter[l], 1);
            __syncthreads();
            const int tile = s_tile;
            if (tile >= NTILES) break;

            const int t0    = (tile & 31) << 7;
            const int cb    = (tile >> 5) & 7;
            const int b     = tile >> 8;
            const int cout0 = cb << 5;
            const __half* Xb = X + (size_t)b * 4 * PLANE;

#define ISSUE_CC(CC) do {                                                        \
            uint32_t _mb = sb + MB_OFF + sI * 8;                                 \
            uint32_t _st = sb + sI * STAGE_BYTES;                                \
            int _sh = ((CC) >= 4) ? dil : 0;                                     \
            int _kc = (CC) & 3;                                                  \
            MBARRIER_EXPECT_TX(_mb, STAGE_TX);                                   \
            bulk_ld(_st,         Xb + ((size_t)_kc * PROWS + GUARD + t0 - _sh) * 64, 16384, _mb); \
            bulk_ld(_st + 16384, Wl + ((size_t)(CC) * 8 + cb) * 4096, 8192, _mb); \
        } while (0)

            // prologue: 3 chunk issues (tid 0), counters advance uniformly
#pragma unroll
            for (int j = 0; j < 3; ++j) {
                if (tid == 0) {
                    if (issued >= 3)
                        MBARRIER_WAIT_PARITY(sb + MB_OFF + 24 + sI * 8, (fI + 1) & 1);
                    ISSUE_CC(j);
                }
                if (++sI == NSTAGE) { sI = 0; ++fI; }
                ++issued;
            }

            float accF[2][2][4], accG[2][2][4];
#pragma unroll
            for (int mi = 0; mi < 2; ++mi)
#pragma unroll
                for (int sN = 0; sN < 2; ++sN)
#pragma unroll
                    for (int e = 0; e < 4; ++e) { accF[mi][sN][e] = 0.f; accG[mi][sN][e] = 0.f; }

            for (int cc = 0; cc < NCHUNK; ++cc) {
                MBARRIER_WAIT_PARITY(sb + MB_OFF + sC * 8, fC & 1);

                const int shift = (cc >= 4) ? dil : 0;
                const uint32_t sA  = sb + sC * STAGE_BYTES;
                const uint32_t sWF = sA + 16384;
                const uint32_t sWG = sA + 20480;
                const uint32_t akey = (uint32_t)((a_row - shift) & 7);

#pragma unroll
                for (int ks = 0; ks < 4; ++ks) {
                    const uint32_t qa = (((uint32_t)(ks * 2) + a_q0) ^ akey) * 16;
                    uint32_t aT[2][4], bF[4], bG[4];
                    ldsm4(aT[0], sA + aoff0 + qa);
                    ldsm4(aT[1], sA + aoff1 + qa);
                    ldsm4(bF, sWF + boff + qbv[ks]);
                    ldsm4(bG, sWG + boff + qbv[ks]);
#pragma unroll
                    for (int mi = 0; mi < 2; ++mi)
#pragma unroll
                        for (int sN = 0; sN < 2; ++sN) {
                            mma16816(accF[mi][sN], aT[mi], &bF[sN * 2]);
                            mma16816(accG[mi][sN], aT[mi], &bG[sN * 2]);
                        }
                }

                if (lane == 0) MBARRIER_ARRIVE(sb + MB_OFF + 24 + sC * 8);
                if (cc + 3 < NCHUNK) {
                    if (lane == 0 && wid == cc) {
                        MBARRIER_WAIT_PARITY(sb + MB_OFF + 24 + sI * 8, (fI + 1) & 1);
                        ISSUE_CC(cc + 3);
                    }
                    if (++sI == NSTAGE) { sI = 0; ++fI; }
                    ++issued;
                }
                if (++sC == NSTAGE) { sC = 0; ++fC; }
            }
#undef ISSUE_CC

            __syncthreads();   // all warps done before smem reuse as z tile

            // ---- epilogue: z tile [t][c] (stride 36), MUFU activations ------
            float* zs = reinterpret_cast<float*>(smem);   // 128 x 36 f32
            {
                const int g  = lane >> 2;
                const int tg = lane & 3;
                float fbv[2][2], gbv[2][2];
#pragma unroll
                for (int sN = 0; sN < 2; ++sN)
#pragma unroll
                    for (int p = 0; p < 2; ++p) {
                        int cout = cout0 + n0 + sN * 8 + 2 * tg + p;
                        fbv[sN][p] = __ldg(fb + cout);
                        gbv[sN][p] = __ldg(gb + cout);
                    }
#pragma unroll
                for (int mi = 0; mi < 2; ++mi)
#pragma unroll
                    for (int sN = 0; sN < 2; ++sN)
#pragma unroll
                        for (int e = 0; e < 4; ++e) {
                            int t_loc = m0 + mi * 16 + g + (e >> 1) * 8;
                            int c_loc = n0 + sN * 8 + 2 * tg + (e & 1);
                            float F = accF[mi][sN][e] + fbv[sN][e & 1];
                            float G = accG[mi][sN][e] + gbv[sN][e & 1];
                            // tanh(F) = 1 - 2/(e^{2F}+1); sigmoid(G) = 1/(1+e^{-G})
                            float th = 1.0f - __fdividef(2.0f, __expf(2.0f * F) + 1.0f);
                            float sg = __fdividef(1.0f, 1.0f + __expf(-G));
                            zs[t_loc * 36 + c_loc] = th * sg;
                        }
            }
            __syncthreads();

            // Y planes: swizzled quad stores
            const int kc = cout0 >> 6;
            const int qb0 = (cout0 & 32) >> 3;   // 0 or 4
#pragma unroll
            for (int i = 0; i < 2; ++i) {
                int id = tid + i * 256;          // 512 total
                int q8 = id & 3, t = id >> 2;
                const float* zr = zs + t * 36 + q8 * 8;
                float4 z0 = reinterpret_cast<const float4*>(zr)[0];
                float4 z1 = reinterpret_cast<const float4*>(zr)[1];
                float zv[8] = { z0.x, z0.y, z0.z, z0.w, z1.x, z1.y, z1.z, z1.w };
                uint32_t pk[4];
#pragma unroll
                for (int p = 0; p < 4; ++p) {
                    __half h0 = __float2half_rn(zv[2 * p]);
                    __half h1 = __float2half_rn(zv[2 * p + 1]);
                    pk[p] = (uint32_t)__half_as_ushort(h0) | ((uint32_t)__half_as_ushort(h1) << 16);
                }
                int tgl = t0 + t;
                int swq = (qb0 + q8) ^ (tgl & 7);
                __half* dst = Y + (((size_t)b * 4 + kc) * PROWS + GUARD + tgl) * 64 + swq * 8;
                *reinterpret_cast<uint4*>(dst) = make_uint4(pk[0], pk[1], pk[2], pk[3]);
            }
            // Zout: [b][c][t] f32
            const size_t zb = (size_t)b * CHAN * TLEN;
#pragma unroll
            for (int i = 0; i < 16; ++i) {
                int id = tid + i * 256;          // 4096 total
                int t = id & 127, cl = id >> 7;
                float z = zs[t * 36 + cl];
                size_t o = zb + (size_t)(cout0 + cl) * TLEN + t0 + t;
                if (first) Zout[o] = z;
                else       Zout[o] += z;
            }
        }   // tile loop

        // ---- inter-layer global barrier (all nCTA co-resident) -------------
        if (tid == 0) {
            __threadfence();
            atomicAdd(&g_arrive[l], 1);
            while (*(volatile int*)&g_arrive[l] < nCTA) __nanosleep(128);
        }
        __syncthreads();
        __threadfence();
    }   // layer loop
}

// ---------------- launch ----------------------------------------------------
extern "C" void kernel_launch(void* const* d_in, const int* in_sizes, int n_in,
                              void* d_out, int out_size) {
    const float* ys = (const float*)d_in[0];
    const float* fw = (const float*)d_in[1];
    const float* fb = (const float*)d_in[2];
    const float* gw = (const float*)d_in[3];
    const float* gb = (const float*)d_in[4];
    float* out = (float*)d_out;

    __half *xA, *xB, *wh;
    cudaGetSymbolAddress((void**)&xA, g_xA);
    cudaGetSymbolAddress((void**)&xB, g_xB);
    cudaGetSymbolAddress((void**)&wh, g_w2);

    cudaFuncSetAttribute(wavenet_persistent,
                         cudaFuncAttributeMaxDynamicSharedMemorySize, SM_TOTAL);
    int nb = 0, smc = 0;
    cudaOccupancyMaxActiveBlocksPerMultiprocessor(&nb, wavenet_persistent, 256, SM_TOTAL);
    cudaDeviceGetAttribute(&smc, cudaDevAttrMultiProcessorCount, 0);
    if (nb < 1) nb = 1;
    const int ncta = nb * smc;

    init_sync<<<1, 32>>>();
    {
        const size_t gz = (size_t)2 * BATCH * 4 * GUARD * 64;
        zero_guards<<<(int)((gz + 255) / 256), 256>>>();
        const int total = NLAYERS * 2 * 8 * 256 * 64;
        prep_weights<<<(total + 255) / 256, 256>>>(fw, gw);
        dim3 tg(TLEN / 32, CHAN / 32, BATCH);
        prep_input<<<tg, dim3(32, 8)>>>(ys);
    }

    wavenet_persistent<<<ncta, 256, SM_TOTAL>>>(xA, xB, wh, fb, gb, out, ncta);
}